// round 2
// baseline (speedup 1.0000x reference)
#include <cuda_runtime.h>
#include <math.h>
#include <stdint.h>

// Problem constants
#define SDIM 2048
#define EDIM 2048
#define NH   16
#define NKV  4
#define DH   128
#define NHG  12
#define RDIM 32
#define NSYM 4
#define RLD  (NHG*RDIM)   // 384
#define KVLD (NKV*DH)     // 512

// Scratch (device globals: allocation-free rule)
static __device__ float g_q [SDIM*EDIM];
static __device__ float g_k [SDIM*KVLD];
static __device__ float g_v [SDIM*KVLD];
static __device__ float g_rq[SDIM*RLD];
static __device__ float g_rk[SDIM*RLD];
static __device__ float g_sc[(size_t)NH*SDIM*SDIM];   // scores / attn (256 MB)
static __device__ float g_ao[SDIM*EDIM];

// ---------------------------------------------------------------------------
// Generic NT GEMM: C[M,N] = A[M,K] @ B[N,K]^T. 128x128 tile, 256 thr, 8x8 micro.
// Requires M,N multiples of 128; K multiple of 8; all ld multiples of 4.
// ---------------------------------------------------------------------------
__global__ __launch_bounds__(256) void gemm_nt(
    const float* __restrict__ A, int lda,
    const float* __restrict__ B, int ldb,
    float* __restrict__ C, int ldc, int K)
{
    __shared__ float As[8][128];
    __shared__ float Bs[8][128];
    const int tid = threadIdx.x;
    const int ty = tid >> 4, tx = tid & 15;
    const int m0 = blockIdx.y << 7, n0 = blockIdx.x << 7;
    const int lrow = tid >> 1;
    const int lc4  = (tid & 1) << 2;
    const float* Ap = A + (size_t)(m0 + lrow) * lda + lc4;
    const float* Bp = B + (size_t)(n0 + lrow) * ldb + lc4;

    float acc[8][8];
#pragma unroll
    for (int i = 0; i < 8; i++)
#pragma unroll
        for (int j = 0; j < 8; j++) acc[i][j] = 0.f;

    for (int k0 = 0; k0 < K; k0 += 8) {
        float4 av = *(const float4*)(Ap + k0);
        float4 bv = *(const float4*)(Bp + k0);
        As[lc4+0][lrow] = av.x; As[lc4+1][lrow] = av.y;
        As[lc4+2][lrow] = av.z; As[lc4+3][lrow] = av.w;
        Bs[lc4+0][lrow] = bv.x; Bs[lc4+1][lrow] = bv.y;
        Bs[lc4+2][lrow] = bv.z; Bs[lc4+3][lrow] = bv.w;
        __syncthreads();
#pragma unroll
        for (int kk = 0; kk < 8; kk++) {
            float4 a0 = *(const float4*)&As[kk][ty*8];
            float4 a1 = *(const float4*)&As[kk][ty*8+4];
            float4 b0 = *(const float4*)&Bs[kk][tx*8];
            float4 b1 = *(const float4*)&Bs[kk][tx*8+4];
            float a[8] = {a0.x,a0.y,a0.z,a0.w,a1.x,a1.y,a1.z,a1.w};
            float b[8] = {b0.x,b0.y,b0.z,b0.w,b1.x,b1.y,b1.z,b1.w};
#pragma unroll
            for (int i = 0; i < 8; i++)
#pragma unroll
                for (int j = 0; j < 8; j++)
                    acc[i][j] = fmaf(a[i], b[j], acc[i][j]);
        }
        __syncthreads();
    }
#pragma unroll
    for (int i = 0; i < 8; i++) {
        float* Cp = C + (size_t)(m0 + ty*8 + i) * ldc + n0 + tx*8;
        *(float4*)(Cp)   = make_float4(acc[i][0],acc[i][1],acc[i][2],acc[i][3]);
        *(float4*)(Cp+4) = make_float4(acc[i][4],acc[i][5],acc[i][6],acc[i][7]);
    }
}

// ---------------------------------------------------------------------------
// Fused RMSNorm + RoPE over one (s, head). 128 threads, one per dim.
// ---------------------------------------------------------------------------
__global__ __launch_bounds__(128) void norm_rope(
    float* __restrict__ buf, const float* __restrict__ w, int ld)
{
    const int s = blockIdx.x, h = blockIdx.y, d = threadIdx.x;
    float* p = buf + (size_t)s * ld + h * DH;
    float v = p[d];
    float ss = v * v;
#pragma unroll
    for (int o = 16; o; o >>= 1) ss += __shfl_xor_sync(0xffffffffu, ss, o);
    __shared__ float r4[4];
    __shared__ float sh[DH];
    if ((d & 31) == 0) r4[d >> 5] = ss;
    __syncthreads();
    float tot = r4[0] + r4[1] + r4[2] + r4[3];
    float nv = v * rsqrtf(tot * (1.f / DH) + 1e-6f) * w[d];
    sh[d] = nv;
    __syncthreads();
    const int dm = d & 63;
    float e = (float)(2 * dm) * (1.f / DH);
    float f = 1.f / powf(10000.f, e);
    float ang = (float)s * f;
    float cs, sn;
    sincosf(ang, &sn, &cs);
    float rot = (d < 64) ? -sh[d + 64] : sh[d - 64];
    p[d] = nv * cs + rot * sn;
}

// ---------------------------------------------------------------------------
// Scores: for each head, lower-triangular 128x128 tiles of
//   scores = (q·k^T)*scale + bias, causal-masked entries written as 0
//   bias (h<12): gs * Rq_i·Rk_j   (h<4: gs*0.5*(Rq_i·Rk_j + Rq_j·Rk_i))
// ---------------------------------------------------------------------------
__global__ __launch_bounds__(256) void scores_kernel(const float* __restrict__ gscale)
{
    __shared__ float As[8][128];
    __shared__ float Bs[8][128];
    __shared__ float Rq_s[128][33];
    __shared__ float Rk_s[128][33];

    const int h = blockIdx.y;
    const int idx = blockIdx.x;
    int ti = (int)((sqrtf(8.f * idx + 1.f) - 1.f) * 0.5f);
    while ((ti + 1) * (ti + 2) / 2 <= idx) ti++;
    while (ti * (ti + 1) / 2 > idx) ti--;
    const int tj = idx - ti * (ti + 1) / 2;
    const int i0 = ti << 7, j0 = tj << 7;

    const int tid = threadIdx.x;
    const int ty = tid >> 4, tx = tid & 15;
    const int lrow = tid >> 1, lc4 = (tid & 1) << 2;
    const int kvh = h >> 2;

    const float* Ap = g_q + (size_t)(i0 + lrow) * EDIM + h * DH + lc4;
    const float* Bp = g_k + (size_t)(j0 + lrow) * KVLD + kvh * DH + lc4;

    float acc[8][8];
#pragma unroll
    for (int i = 0; i < 8; i++)
#pragma unroll
        for (int j = 0; j < 8; j++) acc[i][j] = 0.f;

    for (int k0 = 0; k0 < DH; k0 += 8) {
        float4 av = *(const float4*)(Ap + k0);
        float4 bv = *(const float4*)(Bp + k0);
        As[lc4+0][lrow] = av.x; As[lc4+1][lrow] = av.y;
        As[lc4+2][lrow] = av.z; As[lc4+3][lrow] = av.w;
        Bs[lc4+0][lrow] = bv.x; Bs[lc4+1][lrow] = bv.y;
        Bs[lc4+2][lrow] = bv.z; Bs[lc4+3][lrow] = bv.w;
        __syncthreads();
#pragma unroll
        for (int kk = 0; kk < 8; kk++) {
            float4 a0 = *(const float4*)&As[kk][ty*8];
            float4 a1 = *(const float4*)&As[kk][ty*8+4];
            float4 b0 = *(const float4*)&Bs[kk][tx*8];
            float4 b1 = *(const float4*)&Bs[kk][tx*8+4];
            float a[8] = {a0.x,a0.y,a0.z,a0.w,a1.x,a1.y,a1.z,a1.w};
            float b[8] = {b0.x,b0.y,b0.z,b0.w,b1.x,b1.y,b1.z,b1.w};
#pragma unroll
            for (int i = 0; i < 8; i++)
#pragma unroll
                for (int j = 0; j < 8; j++)
                    acc[i][j] = fmaf(a[i], b[j], acc[i][j]);
        }
        __syncthreads();
    }

    const float scale = 0.08838834764831845f;  // 1/sqrt(128)
#pragma unroll
    for (int i = 0; i < 8; i++)
#pragma unroll
        for (int j = 0; j < 8; j++) acc[i][j] *= scale;

    if (h < NHG) {
        const float gs  = gscale[h];
        const int   np  = (h < NSYM) ? 2 : 1;
        const float wgs = gs * ((h < NSYM) ? 0.5f : 1.f);
        for (int p = 0; p < np; p++) {
            const int rqr = p ? j0 : i0;  // Rq rows loaded
            const int rkr = p ? i0 : j0;  // Rk rows loaded
#pragma unroll
            for (int it = 0; it < 4; it++) {
                int lin = tid + it * 256;
                int row = lin >> 3;
                int c4  = (lin & 7) << 2;
                float4 a = *(const float4*)(g_rq + (size_t)(rqr + row) * RLD + h * RDIM + c4);
                float4 b = *(const float4*)(g_rk + (size_t)(rkr + row) * RLD + h * RDIM + c4);
                Rq_s[row][c4+0]=a.x; Rq_s[row][c4+1]=a.y; Rq_s[row][c4+2]=a.z; Rq_s[row][c4+3]=a.w;
                Rk_s[row][c4+0]=b.x; Rk_s[row][c4+1]=b.y; Rk_s[row][c4+2]=b.z; Rk_s[row][c4+3]=b.w;
            }
            __syncthreads();
#pragma unroll 8
            for (int r = 0; r < RDIM; r++) {
                float a[8], b[8];
                if (p == 0) {
#pragma unroll
                    for (int i = 0; i < 8; i++) a[i] = Rq_s[ty*8+i][r] * wgs;
#pragma unroll
                    for (int j = 0; j < 8; j++) b[j] = Rk_s[tx*8+j][r];
                } else {
#pragma unroll
                    for (int i = 0; i < 8; i++) a[i] = Rk_s[ty*8+i][r] * wgs;
#pragma unroll
                    for (int j = 0; j < 8; j++) b[j] = Rq_s[tx*8+j][r];
                }
#pragma unroll
                for (int i = 0; i < 8; i++)
#pragma unroll
                    for (int j = 0; j < 8; j++)
                        acc[i][j] = fmaf(a[i], b[j], acc[i][j]);
            }
            __syncthreads();
        }
    }

#pragma unroll
    for (int i = 0; i < 8; i++) {
        const int gi = i0 + ty*8 + i;
        float* Cp = g_sc + ((size_t)h * SDIM + gi) * SDIM + j0 + tx*8;
#pragma unroll
        for (int j = 0; j < 8; j++) {
            const int gj = j0 + tx*8 + j;
            Cp[j] = (gj <= gi) ? acc[i][j] : 0.f;  // masked -> 0, never read by softmax
        }
    }
}

// ---------------------------------------------------------------------------
// Row softmax over valid length (i+1); in-place in g_sc. Row cached in smem.
// ---------------------------------------------------------------------------
__global__ __launch_bounds__(256) void softmax_kernel()
{
    const int i = blockIdx.x, h = blockIdx.y;
    const int len = i + 1;
    float* row = g_sc + ((size_t)h * SDIM + i) * SDIM;
    __shared__ float buf[SDIM];
    __shared__ float red[8];
    const int tid = threadIdx.x;

    float m = -3.4e38f;
    for (int j = tid; j < len; j += 256) { float v = row[j]; buf[j] = v; m = fmaxf(m, v); }
#pragma unroll
    for (int o = 16; o; o >>= 1) m = fmaxf(m, __shfl_xor_sync(0xffffffffu, m, o));
    if ((tid & 31) == 0) red[tid >> 5] = m;
    __syncthreads();
    m = red[0];
#pragma unroll
    for (int q = 1; q < 8; q++) m = fmaxf(m, red[q]);
    __syncthreads();

    float sum = 0.f;
    for (int j = tid; j < len; j += 256) { float e = __expf(buf[j] - m); buf[j] = e; sum += e; }
#pragma unroll
    for (int o = 16; o; o >>= 1) sum += __shfl_xor_sync(0xffffffffu, sum, o);
    if ((tid & 31) == 0) red[tid >> 5] = sum;
    __syncthreads();
    sum = red[0] + red[1] + red[2] + red[3] + red[4] + red[5] + red[6] + red[7];
    const float inv = 1.f / sum;
    for (int j = tid; j < len; j += 256) row[j] = buf[j] * inv;
}

// ---------------------------------------------------------------------------
// AV: out[i, h*128+d] = sum_j attn[h,i,j] * v[j, (h/4)*128+d]; causal K-trunc.
// ---------------------------------------------------------------------------
__global__ __launch_bounds__(256) void gemm_av()
{
    __shared__ float As[8][128];
    __shared__ float Bs[8][128];
    const int h = blockIdx.y;
    const int m0 = blockIdx.x << 7;
    const int kvh = h >> 2;
    const int tid = threadIdx.x;
    const int ty = tid >> 4, tx = tid & 15;
    const int lrow = tid >> 1, lc4 = (tid & 1) << 2;
    const int brow = tid >> 5, bc4 = (tid & 31) << 2;

    const float* Ap = g_sc + ((size_t)h * SDIM + m0 + lrow) * SDIM + lc4;
    const float* Bp = g_v + kvh * DH + bc4;

    float acc[8][8];
#pragma unroll
    for (int i = 0; i < 8; i++)
#pragma unroll
        for (int j = 0; j < 8; j++) acc[i][j] = 0.f;

    const int kmax = m0 + 128;  // attn is 0 above the diagonal within the tile band
    for (int k0 = 0; k0 < kmax; k0 += 8) {
        float4 av = *(const float4*)(Ap + k0);
        float4 bv = *(const float4*)(Bp + (size_t)(k0 + brow) * KVLD);
        As[lc4+0][lrow] = av.x; As[lc4+1][lrow] = av.y;
        As[lc4+2][lrow] = av.z; As[lc4+3][lrow] = av.w;
        *(float4*)&Bs[brow][bc4] = bv;
        __syncthreads();
#pragma unroll
        for (int kk = 0; kk < 8; kk++) {
            float4 a0 = *(const float4*)&As[kk][ty*8];
            float4 a1 = *(const float4*)&As[kk][ty*8+4];
            float4 b0 = *(const float4*)&Bs[kk][tx*8];
            float4 b1 = *(const float4*)&Bs[kk][tx*8+4];
            float a[8] = {a0.x,a0.y,a0.z,a0.w,a1.x,a1.y,a1.z,a1.w};
            float b[8] = {b0.x,b0.y,b0.z,b0.w,b1.x,b1.y,b1.z,b1.w};
#pragma unroll
            for (int i = 0; i < 8; i++)
#pragma unroll
                for (int j = 0; j < 8; j++)
                    acc[i][j] = fmaf(a[i], b[j], acc[i][j]);
        }
        __syncthreads();
    }
#pragma unroll
    for (int i = 0; i < 8; i++) {
        float* Cp = g_ao + (size_t)(m0 + ty*8 + i) * EDIM + h * DH + tx*8;
        *(float4*)(Cp)   = make_float4(acc[i][0],acc[i][1],acc[i][2],acc[i][3]);
        *(float4*)(Cp+4) = make_float4(acc[i][4],acc[i][5],acc[i][6],acc[i][7]);
    }
}

// ---------------------------------------------------------------------------
extern "C" void kernel_launch(void* const* d_in, const int* in_sizes, int n_in,
                              void* d_out, int out_size)
{
    const float* x   = (const float*)d_in[0];
    const float* Wq  = (const float*)d_in[1];
    const float* Wk  = (const float*)d_in[2];
    const float* Wv  = (const float*)d_in[3];
    const float* Wo  = (const float*)d_in[4];
    const float* qnw = (const float*)d_in[5];
    const float* knw = (const float*)d_in[6];
    const float* Wrq = (const float*)d_in[7];
    const float* Wrk = (const float*)d_in[8];
    const float* gsc = (const float*)d_in[9];
    float* out = (float*)d_out;

    float *q, *k, *v, *rq, *rk, *ao;
    cudaGetSymbolAddress((void**)&q,  g_q);
    cudaGetSymbolAddress((void**)&k,  g_k);
    cudaGetSymbolAddress((void**)&v,  g_v);
    cudaGetSymbolAddress((void**)&rq, g_rq);
    cudaGetSymbolAddress((void**)&rk, g_rk);
    cudaGetSymbolAddress((void**)&ao, g_ao);

    // Projections
    gemm_nt<<<dim3(16,16), 256>>>(x, EDIM, Wq,  EDIM, q,  EDIM, EDIM);
    gemm_nt<<<dim3(4, 16), 256>>>(x, EDIM, Wk,  EDIM, k,  KVLD, EDIM);
    gemm_nt<<<dim3(4, 16), 256>>>(x, EDIM, Wv,  EDIM, v,  KVLD, EDIM);
    gemm_nt<<<dim3(3, 16), 256>>>(x, EDIM, Wrq, EDIM, rq, RLD,  EDIM);
    gemm_nt<<<dim3(3, 16), 256>>>(x, EDIM, Wrk, EDIM, rk, RLD,  EDIM);

    // RMSNorm + RoPE
    norm_rope<<<dim3(SDIM, NH),  128>>>(q, qnw, EDIM);
    norm_rope<<<dim3(SDIM, NKV), 128>>>(k, knw, KVLD);

    // Scores (+bias, causal), softmax, AV
    scores_kernel<<<dim3(136, NH), 256>>>(gsc);
    softmax_kernel<<<dim3(SDIM, NH), 256>>>();
    gemm_av<<<dim3(16, NH), 256>>>();

    // Output projection
    gemm_nt<<<dim3(16,16), 256>>>(ao, EDIM, Wo, EDIM, out, EDIM, EDIM);
}

// round 4
// speedup vs baseline: 1.9765x; 1.9765x over previous
#include <cuda_runtime.h>
#include <cuda_bf16.h>
#include <math.h>
#include <stdint.h>

#define SDIM 2048
#define EDIM 2048
#define NH   16
#define NKV  4
#define DH   128
#define NHG  12
#define RDIM 32
#define NSYM 4
#define RLD  (NHG*RDIM)
#define KVLD (NKV*DH)
#define KP   (3*EDIM)     // 6144, K' after bf16x2 K-folding

static __device__ float g_q [SDIM*EDIM];
static __device__ float g_k [SDIM*KVLD];
static __device__ float g_v [SDIM*KVLD];
static __device__ float g_rq[SDIM*RLD];
static __device__ float g_rk[SDIM*RLD];
static __device__ float g_sc[(size_t)NH*SDIM*SDIM];
static __device__ float g_ao[SDIM*EDIM];

static __device__ __nv_bfloat16 g_x3 [SDIM*KP];
static __device__ __nv_bfloat16 g_ao3[SDIM*KP];
static __device__ __nv_bfloat16 g_wq3[EDIM*KP];
static __device__ __nv_bfloat16 g_wk3[KVLD*KP];
static __device__ __nv_bfloat16 g_wv3[KVLD*KP];
static __device__ __nv_bfloat16 g_wr13[RLD*KP];
static __device__ __nv_bfloat16 g_wr23[RLD*KP];
static __device__ __nv_bfloat16 g_wo3[EDIM*KP];

// ---------------- PTX helpers (sm_80-level only: valid on compute_103) -------
__device__ __forceinline__ uint32_t smem_u32(const void* p) {
    uint32_t a;
    asm("{ .reg .u64 t; cvta.to.shared.u64 t, %1; cvt.u32.u64 %0, t; }" : "=r"(a) : "l"(p));
    return a;
}
__device__ __forceinline__ void cpa16(uint32_t d, const void* g) {
    asm volatile("cp.async.cg.shared.global [%0], [%1], 16;" :: "r"(d), "l"(g));
}
__device__ __forceinline__ void cp_commit() {
    asm volatile("cp.async.commit_group;" ::: "memory");
}
template<int N> __device__ __forceinline__ void cp_wait() {
    asm volatile("cp.async.wait_group %0;" :: "n"(N) : "memory");
}
__device__ __forceinline__ void ldm_x4(uint32_t& r0, uint32_t& r1, uint32_t& r2, uint32_t& r3,
                                       uint32_t addr) {
    asm volatile("ldmatrix.sync.aligned.m8n8.x4.shared.b16 {%0,%1,%2,%3}, [%4];"
                 : "=r"(r0), "=r"(r1), "=r"(r2), "=r"(r3) : "r"(addr));
}
__device__ __forceinline__ void mma_bf16(float* d, const uint32_t* a, const uint32_t* b) {
    asm volatile("mma.sync.aligned.m16n8k16.row.col.f32.bf16.bf16.f32 "
                 "{%0,%1,%2,%3}, {%4,%5,%6,%7}, {%8,%9}, {%0,%1,%2,%3};"
                 : "+f"(d[0]), "+f"(d[1]), "+f"(d[2]), "+f"(d[3])
                 : "r"(a[0]), "r"(a[1]), "r"(a[2]), "r"(a[3]), "r"(b[0]), "r"(b[1]));
}

// ---------------- bf16x2 K-fold split ----------------------------------------
// src row-major [M][2048] fp32 -> dst [M][6144] bf16.
// isB=0 (A side): (h,h,l) per k.  isB=1 (B side): (h,l,h) per k.
__global__ __launch_bounds__(256) void split_pair(
    const float* __restrict__ s, __nv_bfloat16* __restrict__ d, int npairs, int isB)
{
    int i = blockIdx.x * 256 + threadIdx.x;
    if (i >= npairs) return;
    float2 v = ((const float2*)s)[i];
    __nv_bfloat16 h0 = __float2bfloat16(v.x);
    __nv_bfloat16 l0 = __float2bfloat16(v.x - __bfloat162float(h0));
    __nv_bfloat16 h1 = __float2bfloat16(v.y);
    __nv_bfloat16 l1 = __float2bfloat16(v.y - __bfloat162float(h1));
    uint32_t H0 = __bfloat16_as_ushort(h0), L0 = __bfloat16_as_ushort(l0);
    uint32_t H1 = __bfloat16_as_ushort(h1), L1 = __bfloat16_as_ushort(l1);
    uint32_t w0, w1, w2;
    if (!isB) { w0 = H0 | (H0 << 16); w1 = L0 | (H1 << 16); w2 = H1 | (L1 << 16); }
    else      { w0 = H0 | (L0 << 16); w1 = H0 | (H1 << 16); w2 = L1 | (H1 << 16); }
    uint32_t* o = (uint32_t*)d + 3 * (size_t)i;
    o[0] = w0; o[1] = w1; o[2] = w2;
}

// ---------------- bf16 NT GEMM on tensor cores (mma.sync) --------------------
// C[M,N] fp32 = A[M,kp] bf16 * B[N,kp]^T. 128x128 CTA tile, 8 warps (2x4),
// BK=64, XOR-swizzled smem, ldmatrix.x4, cp.async double-buffered.
__global__ __launch_bounds__(256) void gemm_bf16(
    const __nv_bfloat16* __restrict__ A, const __nv_bfloat16* __restrict__ B,
    float* __restrict__ C, int ldc, int kp)
{
    extern __shared__ __align__(1024) char dsm[];
    const uint32_t sb = smem_u32(dsm);
    const int tid = threadIdx.x;
    const int l = tid & 31, wid = tid >> 5;
    const int wm = wid & 1, wn = wid >> 1;
    const int m0 = blockIdx.y << 7, n0 = blockIdx.x << 7;
    const int steps = kp >> 6;

    float acc[4][4][4];
#pragma unroll
    for (int i = 0; i < 4; i++)
#pragma unroll
        for (int j = 0; j < 4; j++)
#pragma unroll
            for (int r = 0; r < 4; r++) acc[i][j][r] = 0.f;

    // cp.async thread mapping: 1024 16B-chunks per 128x64 tile, 4 per thread
    const int c0row0 = tid >> 3;           // + 32*i
    const int cch    = tid & 7;

    // ldmatrix lane bases (block-local rows)
    const int ar = wm * 64 + (l & 7) + (l & 8);
    const int br = wn * 32 + (l & 7) + 8 * (l >> 4);
    const int akh = (l >> 4);              // A k-half from bit4
    const int bkh = (l >> 3) & 1;          // B k-half from bit3
    const int lsw = l & 7;

#define LOAD_TILE(bufi, stepi) do {                                              \
    uint32_t base = sb + (bufi) * 32768u;                                        \
    const __nv_bfloat16* Ag = A + (size_t)m0 * kp + (size_t)(stepi) * 64;        \
    const __nv_bfloat16* Bg = B + (size_t)n0 * kp + (size_t)(stepi) * 64;        \
    _Pragma("unroll")                                                            \
    for (int it = 0; it < 4; it++) {                                             \
        int row = c0row0 + 32 * it;                                              \
        uint32_t sw = row * 128u + 16u * (cch ^ (row & 7));                      \
        cpa16(base + sw,          Ag + (size_t)row * kp + cch * 8);              \
        cpa16(base + 16384u + sw, Bg + (size_t)row * kp + cch * 8);              \
    } } while (0)

    LOAD_TILE(0, 0);
    cp_commit();

    for (int s = 0; s < steps; s++) {
        const int buf = s & 1;
        if (s + 1 < steps) { LOAD_TILE((s + 1) & 1, s + 1); cp_commit(); cp_wait<1>(); }
        else cp_wait<0>();
        __syncthreads();

        const uint32_t Ab = sb + buf * 32768u;
        const uint32_t Bb = Ab + 16384u;
#pragma unroll
        for (int kk = 0; kk < 4; kk++) {
            uint32_t af[4][4], bf[4][2];
#pragma unroll
            for (int tm = 0; tm < 4; tm++)
                ldm_x4(af[tm][0], af[tm][1], af[tm][2], af[tm][3],
                       Ab + (uint32_t)(ar + tm * 16) * 128u
                          + 16u * (((kk << 1) + akh) ^ lsw));
#pragma unroll
            for (int np = 0; np < 2; np++) {
                uint32_t r0, r1, r2, r3;
                ldm_x4(r0, r1, r2, r3,
                       Bb + (uint32_t)(br + np * 16) * 128u
                          + 16u * (((kk << 1) + bkh) ^ lsw));
                bf[2*np][0] = r0; bf[2*np][1] = r1;
                bf[2*np+1][0] = r2; bf[2*np+1][1] = r3;
            }
#pragma unroll
            for (int tm = 0; tm < 4; tm++)
#pragma unroll
                for (int tn = 0; tn < 4; tn++)
                    mma_bf16(acc[tm][tn], af[tm], bf[tn]);
        }
        __syncthreads();
    }

    // Epilogue
    const int er = m0 + wm * 64 + (l >> 2);
    const int ec = n0 + wn * 32 + 2 * (l & 3);
#pragma unroll
    for (int tm = 0; tm < 4; tm++)
#pragma unroll
        for (int tn = 0; tn < 4; tn++) {
            float* p0 = C + (size_t)(er + tm * 16) * ldc + ec + tn * 8;
            float* p1 = C + (size_t)(er + tm * 16 + 8) * ldc + ec + tn * 8;
            *(float2*)p0 = make_float2(acc[tm][tn][0], acc[tm][tn][1]);
            *(float2*)p1 = make_float2(acc[tm][tn][2], acc[tm][tn][3]);
        }
#undef LOAD_TILE
}

// ---------------- RMSNorm + RoPE ----------------
__global__ __launch_bounds__(128) void norm_rope(
    float* __restrict__ buf, const float* __restrict__ w, int ld)
{
    const int s = blockIdx.x, h = blockIdx.y, d = threadIdx.x;
    float* p = buf + (size_t)s * ld + h * DH;
    float v = p[d];
    float ss = v * v;
#pragma unroll
    for (int o = 16; o; o >>= 1) ss += __shfl_xor_sync(0xffffffffu, ss, o);
    __shared__ float r4[4];
    __shared__ float sh[DH];
    if ((d & 31) == 0) r4[d >> 5] = ss;
    __syncthreads();
    float tot = r4[0] + r4[1] + r4[2] + r4[3];
    float nv = v * rsqrtf(tot * (1.f / DH) + 1e-6f) * w[d];
    sh[d] = nv;
    __syncthreads();
    const int dm = d & 63;
    float f = 1.f / powf(10000.f, (float)(2 * dm) * (1.f / DH));
    float cs, sn;
    sincosf((float)s * f, &sn, &cs);
    float rot = (d < 64) ? -sh[d + 64] : sh[d - 64];
    p[d] = nv * cs + rot * sn;
}

// ---------------- Scores ----------------
__global__ __launch_bounds__(256) void scores_kernel(const float* __restrict__ gscale)
{
    __shared__ float As[8][128];
    __shared__ float Bs[8][128];
    __shared__ float Rq_s[128][33];
    __shared__ float Rk_s[128][33];

    const int h = blockIdx.y;
    const int idx = blockIdx.x;
    int ti = (int)((sqrtf(8.f * idx + 1.f) - 1.f) * 0.5f);
    while ((ti + 1) * (ti + 2) / 2 <= idx) ti++;
    while (ti * (ti + 1) / 2 > idx) ti--;
    const int tj = idx - ti * (ti + 1) / 2;
    const int i0 = ti << 7, j0 = tj << 7;

    const int tid = threadIdx.x;
    const int ty = tid >> 4, tx = tid & 15;
    const int lrow = tid >> 1, lc4 = (tid & 1) << 2;
    const int kvh = h >> 2;

    const float* Ap = g_q + (size_t)(i0 + lrow) * EDIM + h * DH + lc4;
    const float* Bp = g_k + (size_t)(j0 + lrow) * KVLD + kvh * DH + lc4;

    float acc[8][8];
#pragma unroll
    for (int i = 0; i < 8; i++)
#pragma unroll
        for (int j = 0; j < 8; j++) acc[i][j] = 0.f;

    for (int k0 = 0; k0 < DH; k0 += 8) {
        float4 av = *(const float4*)(Ap + k0);
        float4 bv = *(const float4*)(Bp + k0);
        As[lc4+0][lrow] = av.x; As[lc4+1][lrow] = av.y;
        As[lc4+2][lrow] = av.z; As[lc4+3][lrow] = av.w;
        Bs[lc4+0][lrow] = bv.x; Bs[lc4+1][lrow] = bv.y;
        Bs[lc4+2][lrow] = bv.z; Bs[lc4+3][lrow] = bv.w;
        __syncthreads();
#pragma unroll
        for (int kk = 0; kk < 8; kk++) {
            float4 a0 = *(const float4*)&As[kk][ty*8];
            float4 a1 = *(const float4*)&As[kk][ty*8+4];
            float4 b0 = *(const float4*)&Bs[kk][tx*8];
            float4 b1 = *(const float4*)&Bs[kk][tx*8+4];
            float a[8] = {a0.x,a0.y,a0.z,a0.w,a1.x,a1.y,a1.z,a1.w};
            float b[8] = {b0.x,b0.y,b0.z,b0.w,b1.x,b1.y,b1.z,b1.w};
#pragma unroll
            for (int i = 0; i < 8; i++)
#pragma unroll
                for (int j = 0; j < 8; j++)
                    acc[i][j] = fmaf(a[i], b[j], acc[i][j]);
        }
        __syncthreads();
    }

    const float scale = 0.08838834764831845f;
#pragma unroll
    for (int i = 0; i < 8; i++)
#pragma unroll
        for (int j = 0; j < 8; j++) acc[i][j] *= scale;

    if (h < NHG) {
        const float gs  = gscale[h];
        const int   np  = (h < NSYM) ? 2 : 1;
        const float wgs = gs * ((h < NSYM) ? 0.5f : 1.f);
        for (int p = 0; p < np; p++) {
            const int rqr = p ? j0 : i0;
            const int rkr = p ? i0 : j0;
#pragma unroll
            for (int it = 0; it < 4; it++) {
                int lin = tid + it * 256;
                int row = lin >> 3;
                int c4  = (lin & 7) << 2;
                float4 a = *(const float4*)(g_rq + (size_t)(rqr + row) * RLD + h * RDIM + c4);
                float4 b = *(const float4*)(g_rk + (size_t)(rkr + row) * RLD + h * RDIM + c4);
                Rq_s[row][c4+0]=a.x; Rq_s[row][c4+1]=a.y; Rq_s[row][c4+2]=a.z; Rq_s[row][c4+3]=a.w;
                Rk_s[row][c4+0]=b.x; Rk_s[row][c4+1]=b.y; Rk_s[row][c4+2]=b.z; Rk_s[row][c4+3]=b.w;
            }
            __syncthreads();
#pragma unroll 8
            for (int r = 0; r < RDIM; r++) {
                float a[8], b[8];
                if (p == 0) {
#pragma unroll
                    for (int i = 0; i < 8; i++) a[i] = Rq_s[ty*8+i][r] * wgs;
#pragma unroll
                    for (int j = 0; j < 8; j++) b[j] = Rk_s[tx*8+j][r];
                } else {
#pragma unroll
                    for (int i = 0; i < 8; i++) a[i] = Rk_s[ty*8+i][r] * wgs;
#pragma unroll
                    for (int j = 0; j < 8; j++) b[j] = Rq_s[tx*8+j][r];
                }
#pragma unroll
                for (int i = 0; i < 8; i++)
#pragma unroll
                    for (int j = 0; j < 8; j++)
                        acc[i][j] = fmaf(a[i], b[j], acc[i][j]);
            }
            __syncthreads();
        }
    }

#pragma unroll
    for (int i = 0; i < 8; i++) {
        const int gi = i0 + ty*8 + i;
        float* Cp = g_sc + ((size_t)h * SDIM + gi) * SDIM + j0 + tx*8;
#pragma unroll
        for (int j = 0; j < 8; j++) {
            const int gj = j0 + tx*8 + j;
            Cp[j] = (gj <= gi) ? acc[i][j] : 0.f;
        }
    }
}

// ---------------- Row softmax ----------------
__global__ __launch_bounds__(256) void softmax_kernel()
{
    const int i = blockIdx.x, h = blockIdx.y;
    const int len = i + 1;
    float* row = g_sc + ((size_t)h * SDIM + i) * SDIM;
    __shared__ float buf[SDIM];
    __shared__ float red[8];
    const int tid = threadIdx.x;

    float m = -3.4e38f;
    for (int j = tid; j < len; j += 256) { float v = row[j]; buf[j] = v; m = fmaxf(m, v); }
#pragma unroll
    for (int o = 16; o; o >>= 1) m = fmaxf(m, __shfl_xor_sync(0xffffffffu, m, o));
    if ((tid & 31) == 0) red[tid >> 5] = m;
    __syncthreads();
    m = red[0];
#pragma unroll
    for (int q = 1; q < 8; q++) m = fmaxf(m, red[q]);
    __syncthreads();

    float sum = 0.f;
    for (int j = tid; j < len; j += 256) { float e = __expf(buf[j] - m); buf[j] = e; sum += e; }
#pragma unroll
    for (int o = 16; o; o >>= 1) sum += __shfl_xor_sync(0xffffffffu, sum, o);
    if ((tid & 31) == 0) red[tid >> 5] = sum;
    __syncthreads();
    sum = red[0] + red[1] + red[2] + red[3] + red[4] + red[5] + red[6] + red[7];
    const float inv = 1.f / sum;
    for (int j = tid; j < len; j += 256) row[j] = buf[j] * inv;
}

// ---------------- AV ----------------
__global__ __launch_bounds__(256) void gemm_av()
{
    __shared__ float As[8][128];
    __shared__ float Bs[8][128];
    const int h = blockIdx.y;
    const int m0 = blockIdx.x << 7;
    const int kvh = h >> 2;
    const int tid = threadIdx.x;
    const int ty = tid >> 4, tx = tid & 15;
    const int lrow = tid >> 1, lc4 = (tid & 1) << 2;
    const int brow = tid >> 5, bc4 = (tid & 31) << 2;

    const float* Ap = g_sc + ((size_t)h * SDIM + m0 + lrow) * SDIM + lc4;
    const float* Bp = g_v + kvh * DH + bc4;

    float acc[8][8];
#pragma unroll
    for (int i = 0; i < 8; i++)
#pragma unroll
        for (int j = 0; j < 8; j++) acc[i][j] = 0.f;

    const int kmax = m0 + 128;
    for (int k0 = 0; k0 < kmax; k0 += 8) {
        float4 av = *(const float4*)(Ap + k0);
        float4 bv = *(const float4*)(Bp + (size_t)(k0 + brow) * KVLD);
        As[lc4+0][lrow] = av.x; As[lc4+1][lrow] = av.y;
        As[lc4+2][lrow] = av.z; As[lc4+3][lrow] = av.w;
        *(float4*)&Bs[brow][bc4] = bv;
        __syncthreads();
#pragma unroll
        for (int kk = 0; kk < 8; kk++) {
            float4 a0 = *(const float4*)&As[kk][ty*8];
            float4 a1 = *(const float4*)&As[kk][ty*8+4];
            float4 b0 = *(const float4*)&Bs[kk][tx*8];
            float4 b1 = *(const float4*)&Bs[kk][tx*8+4];
            float a[8] = {a0.x,a0.y,a0.z,a0.w,a1.x,a1.y,a1.z,a1.w};
            float b[8] = {b0.x,b0.y,b0.z,b0.w,b1.x,b1.y,b1.z,b1.w};
#pragma unroll
            for (int i = 0; i < 8; i++)
#pragma unroll
                for (int j = 0; j < 8; j++)
                    acc[i][j] = fmaf(a[i], b[j], acc[i][j]);
        }
        __syncthreads();
    }
#pragma unroll
    for (int i = 0; i < 8; i++) {
        float* Cp = g_ao + (size_t)(m0 + ty*8 + i) * EDIM + h * DH + tx*8;
        *(float4*)(Cp)   = make_float4(acc[i][0],acc[i][1],acc[i][2],acc[i][3]);
        *(float4*)(Cp+4) = make_float4(acc[i][4],acc[i][5],acc[i][6],acc[i][7]);
    }
}

// ---------------- Host ----------------
extern "C" void kernel_launch(void* const* d_in, const int* in_sizes, int n_in,
                              void* d_out, int out_size)
{
    const float* x   = (const float*)d_in[0];
    const float* Wq  = (const float*)d_in[1];
    const float* Wk  = (const float*)d_in[2];
    const float* Wv  = (const float*)d_in[3];
    const float* Wo  = (const float*)d_in[4];
    const float* qnw = (const float*)d_in[5];
    const float* knw = (const float*)d_in[6];
    const float* Wrq = (const float*)d_in[7];
    const float* Wrk = (const float*)d_in[8];
    const float* gsc = (const float*)d_in[9];
    float* out = (float*)d_out;

    float *q, *k, *v, *rq, *rk, *ao;
    __nv_bfloat16 *x3, *ao3, *wq3, *wk3, *wv3, *wr13, *wr23, *wo3;
    cudaGetSymbolAddress((void**)&q,  g_q);
    cudaGetSymbolAddress((void**)&k,  g_k);
    cudaGetSymbolAddress((void**)&v,  g_v);
    cudaGetSymbolAddress((void**)&rq, g_rq);
    cudaGetSymbolAddress((void**)&rk, g_rk);
    cudaGetSymbolAddress((void**)&ao, g_ao);
    cudaGetSymbolAddress((void**)&x3,  g_x3);
    cudaGetSymbolAddress((void**)&ao3, g_ao3);
    cudaGetSymbolAddress((void**)&wq3, g_wq3);
    cudaGetSymbolAddress((void**)&wk3, g_wk3);
    cudaGetSymbolAddress((void**)&wv3, g_wv3);
    cudaGetSymbolAddress((void**)&wr13, g_wr13);
    cudaGetSymbolAddress((void**)&wr23, g_wr23);
    cudaGetSymbolAddress((void**)&wo3, g_wo3);

    cudaFuncSetAttribute(gemm_bf16, cudaFuncAttributeMaxDynamicSharedMemorySize, 65536);

    // Splits (A side: x, ao; B side: weights)
    split_pair<<<SDIM*EDIM/512, 256>>>(x,   x3,  SDIM*EDIM/2, 0);
    split_pair<<<EDIM*EDIM/512, 256>>>(Wq,  wq3, EDIM*EDIM/2, 1);
    split_pair<<<KVLD*EDIM/512, 256>>>(Wk,  wk3, KVLD*EDIM/2, 1);
    split_pair<<<KVLD*EDIM/512, 256>>>(Wv,  wv3, KVLD*EDIM/2, 1);
    split_pair<<<RLD*EDIM/512,  256>>>(Wrq, wr13, RLD*EDIM/2, 1);
    split_pair<<<RLD*EDIM/512,  256>>>(Wrk, wr23, RLD*EDIM/2, 1);
    split_pair<<<EDIM*EDIM/512, 256>>>(Wo,  wo3, EDIM*EDIM/2, 1);

    // Projections on tensor cores
    gemm_bf16<<<dim3(16,16), 256, 65536>>>(x3, wq3,  q,  EDIM, KP);
    gemm_bf16<<<dim3(4, 16), 256, 65536>>>(x3, wk3,  k,  KVLD, KP);
    gemm_bf16<<<dim3(4, 16), 256, 65536>>>(x3, wv3,  v,  KVLD, KP);
    gemm_bf16<<<dim3(3, 16), 256, 65536>>>(x3, wr13, rq, RLD,  KP);
    gemm_bf16<<<dim3(3, 16), 256, 65536>>>(x3, wr23, rk, RLD,  KP);

    norm_rope<<<dim3(SDIM, NH),  128>>>(q, qnw, EDIM);
    norm_rope<<<dim3(SDIM, NKV), 128>>>(k, knw, KVLD);

    scores_kernel<<<dim3(136, NH), 256>>>(gsc);
    softmax_kernel<<<dim3(SDIM, NH), 256>>>();
    gemm_av<<<dim3(16, NH), 256>>>();

    // Output projection
    split_pair<<<SDIM*EDIM/512, 256>>>(ao, ao3, SDIM*EDIM/2, 0);
    gemm_bf16<<<dim3(16,16), 256, 65536>>>(ao3, wo3, out, EDIM, KP);
}

// round 5
// speedup vs baseline: 2.2952x; 1.1613x over previous
#include <cuda_runtime.h>
#include <cuda_bf16.h>
#include <math.h>
#include <stdint.h>

#define SDIM 2048
#define EDIM 2048
#define NH   16
#define NKV  4
#define DH   128
#define NHG  12
#define RDIM 32
#define NSYM 4
#define KP   (3*EDIM)     // 6144 folded K
#define NOUT 3840         // Wq|Wk|Wv|Wrq|Wrk concat
#define CQ   0
#define CK   2048
#define CV   2560
#define CRQ  3072
#define CRK  3456

static __device__ float g_pr[SDIM*NOUT];              // all projections
static __device__ float g_sc[(size_t)NH*SDIM*SDIM];   // scores/attn
static __device__ float g_ao[SDIM*EDIM];
static __device__ __nv_bfloat16 g_x3 [SDIM*KP];
static __device__ __nv_bfloat16 g_ao3[SDIM*KP];
static __device__ __nv_bfloat16 g_w3 [(size_t)NOUT*KP];  // folded W_all
static __device__ __nv_bfloat16 g_wo3[(size_t)EDIM*KP];

// ---------------- PTX helpers ----------------
__device__ __forceinline__ uint32_t smem_u32(const void* p) {
    uint32_t a;
    asm("{ .reg .u64 t; cvta.to.shared.u64 t, %1; cvt.u32.u64 %0, t; }" : "=r"(a) : "l"(p));
    return a;
}
__device__ __forceinline__ void cpa16(uint32_t d, const void* g) {
    asm volatile("cp.async.cg.shared.global [%0], [%1], 16;" :: "r"(d), "l"(g));
}
__device__ __forceinline__ void cp_commit() { asm volatile("cp.async.commit_group;" ::: "memory"); }
template<int N> __device__ __forceinline__ void cp_wait() {
    asm volatile("cp.async.wait_group %0;" :: "n"(N) : "memory");
}
__device__ __forceinline__ void ldm_x4(uint32_t& r0, uint32_t& r1, uint32_t& r2, uint32_t& r3,
                                       uint32_t addr) {
    asm volatile("ldmatrix.sync.aligned.m8n8.x4.shared.b16 {%0,%1,%2,%3}, [%4];"
                 : "=r"(r0), "=r"(r1), "=r"(r2), "=r"(r3) : "r"(addr));
}
__device__ __forceinline__ void mma_bf16(float* d, const uint32_t* a, const uint32_t* b) {
    asm volatile("mma.sync.aligned.m16n8k16.row.col.f32.bf16.bf16.f32 "
                 "{%0,%1,%2,%3}, {%4,%5,%6,%7}, {%8,%9}, {%0,%1,%2,%3};"
                 : "+f"(d[0]), "+f"(d[1]), "+f"(d[2]), "+f"(d[3])
                 : "r"(a[0]), "r"(a[1]), "r"(a[2]), "r"(a[3]), "r"(b[0]), "r"(b[1]));
}

// ---------------- bf16x2 K-fold split ----------------
__global__ __launch_bounds__(256) void split_pair(
    const float* __restrict__ s, __nv_bfloat16* __restrict__ d, int npairs, int isB)
{
    int i = blockIdx.x * 256 + threadIdx.x;
    if (i >= npairs) return;
    float2 v = ((const float2*)s)[i];
    __nv_bfloat16 h0 = __float2bfloat16(v.x);
    __nv_bfloat16 l0 = __float2bfloat16(v.x - __bfloat162float(h0));
    __nv_bfloat16 h1 = __float2bfloat16(v.y);
    __nv_bfloat16 l1 = __float2bfloat16(v.y - __bfloat162float(h1));
    uint32_t H0 = __bfloat16_as_ushort(h0), L0 = __bfloat16_as_ushort(l0);
    uint32_t H1 = __bfloat16_as_ushort(h1), L1 = __bfloat16_as_ushort(l1);
    uint32_t w0, w1, w2;
    if (!isB) { w0 = H0 | (H0 << 16); w1 = L0 | (H1 << 16); w2 = H1 | (L1 << 16); }
    else      { w0 = H0 | (L0 << 16); w1 = H0 | (H1 << 16); w2 = L1 | (H1 << 16); }
    uint32_t* o = (uint32_t*)d + 3 * (size_t)i;
    o[0] = w0; o[1] = w1; o[2] = w2;
}

// ---------------- bf16 NT GEMM (mma.sync, 3-stage cp.async) ----------------
__global__ __launch_bounds__(256) void gemm_bf16(
    const __nv_bfloat16* __restrict__ A, const __nv_bfloat16* __restrict__ B,
    float* __restrict__ C, int ldc, int kp)
{
    extern __shared__ __align__(1024) char dsm[];
    const uint32_t sb = smem_u32(dsm);
    const int tid = threadIdx.x;
    const int l = tid & 31, wid = tid >> 5;
    const int wm = wid & 1, wn = wid >> 1;
    const int m0 = blockIdx.y << 7, n0 = blockIdx.x << 7;
    const int steps = kp >> 6;

    float acc[4][4][4];
#pragma unroll
    for (int i = 0; i < 4; i++)
#pragma unroll
        for (int j = 0; j < 4; j++)
#pragma unroll
            for (int r = 0; r < 4; r++) acc[i][j][r] = 0.f;

    const int c0row0 = tid >> 3;
    const int cch    = tid & 7;
    const int ar = wm * 64 + (l & 7) + (l & 8);
    const int br = wn * 32 + (l & 7) + 8 * (l >> 4);
    const int akh = (l >> 4);
    const int bkh = (l >> 3) & 1;
    const int lsw = l & 7;

#define LOAD_TILE(bufi, stepi) do {                                              \
    uint32_t base = sb + (bufi) * 32768u;                                        \
    const __nv_bfloat16* Ag = A + (size_t)m0 * kp + (size_t)(stepi) * 64;        \
    const __nv_bfloat16* Bg = B + (size_t)n0 * kp + (size_t)(stepi) * 64;        \
    _Pragma("unroll")                                                            \
    for (int it = 0; it < 4; it++) {                                             \
        int row = c0row0 + 32 * it;                                              \
        uint32_t sw = row * 128u + 16u * (cch ^ (row & 7));                      \
        cpa16(base + sw,          Ag + (size_t)row * kp + cch * 8);              \
        cpa16(base + 16384u + sw, Bg + (size_t)row * kp + cch * 8);              \
    } } while (0)

    LOAD_TILE(0, 0); cp_commit();
    if (steps > 1) { LOAD_TILE(1, 1); }
    cp_commit();

    for (int s = 0; s < steps; s++) {
        if (s + 2 < steps) {
            int b2 = (s + 2) % 3;
            LOAD_TILE(b2, s + 2);
        }
        cp_commit();
        cp_wait<2>();
        __syncthreads();

        const int buf = s % 3;
        const uint32_t Ab = sb + buf * 32768u;
        const uint32_t Bb = Ab + 16384u;
#pragma unroll
        for (int kk = 0; kk < 4; kk++) {
            uint32_t af[4][4], bf[4][2];
#pragma unroll
            for (int tm = 0; tm < 4; tm++)
                ldm_x4(af[tm][0], af[tm][1], af[tm][2], af[tm][3],
                       Ab + (uint32_t)(ar + tm * 16) * 128u
                          + 16u * (((kk << 1) + akh) ^ lsw));
#pragma unroll
            for (int np = 0; np < 2; np++) {
                uint32_t r0, r1, r2, r3;
                ldm_x4(r0, r1, r2, r3,
                       Bb + (uint32_t)(br + np * 16) * 128u
                          + 16u * (((kk << 1) + bkh) ^ lsw));
                bf[2*np][0] = r0; bf[2*np][1] = r1;
                bf[2*np+1][0] = r2; bf[2*np+1][1] = r3;
            }
#pragma unroll
            for (int tm = 0; tm < 4; tm++)
#pragma unroll
                for (int tn = 0; tn < 4; tn++)
                    mma_bf16(acc[tm][tn], af[tm], bf[tn]);
        }
        __syncthreads();
    }

    const int er = m0 + wm * 64 + (l >> 2);
    const int ec = n0 + wn * 32 + 2 * (l & 3);
#pragma unroll
    for (int tm = 0; tm < 4; tm++)
#pragma unroll
        for (int tn = 0; tn < 4; tn++) {
            float* p0 = C + (size_t)(er + tm * 16) * ldc + ec + tn * 8;
            float* p1 = C + (size_t)(er + tm * 16 + 8) * ldc + ec + tn * 8;
            *(float2*)p0 = make_float2(acc[tm][tn][0], acc[tm][tn][1]);
            *(float2*)p1 = make_float2(acc[tm][tn][2], acc[tm][tn][3]);
        }
#undef LOAD_TILE
}

// ---------------- RMSNorm + RoPE (on g_pr slices, ld=NOUT) ----------------
__global__ __launch_bounds__(128) void norm_rope(
    float* __restrict__ buf, const float* __restrict__ w)
{
    const int s = blockIdx.x, h = blockIdx.y, d = threadIdx.x;
    float* p = buf + (size_t)s * NOUT + h * DH;
    float v = p[d];
    float ss = v * v;
#pragma unroll
    for (int o = 16; o; o >>= 1) ss += __shfl_xor_sync(0xffffffffu, ss, o);
    __shared__ float r4[4];
    __shared__ float sh[DH];
    if ((d & 31) == 0) r4[d >> 5] = ss;
    __syncthreads();
    float tot = r4[0] + r4[1] + r4[2] + r4[3];
    float nv = v * rsqrtf(tot * (1.f / DH) + 1e-6f) * w[d];
    sh[d] = nv;
    __syncthreads();
    const int dm = d & 63;
    float f = 1.f / powf(10000.f, (float)(2 * dm) * (1.f / DH));
    float cs, sn;
    sincosf((float)s * f, &sn, &cs);
    float rot = (d < 64) ? -sh[d + 64] : sh[d - 64];
    p[d] = nv * cs + rot * sn;
}

// ---------------- Scores ----------------
__global__ __launch_bounds__(256) void scores_kernel(const float* __restrict__ gscale)
{
    __shared__ float As[8][128];
    __shared__ float Bs[8][128];
    __shared__ float Rq_s[128][33];
    __shared__ float Rk_s[128][33];

    const int h = blockIdx.y;
    const int idx = blockIdx.x;
    int ti = (int)((sqrtf(8.f * idx + 1.f) - 1.f) * 0.5f);
    while ((ti + 1) * (ti + 2) / 2 <= idx) ti++;
    while (ti * (ti + 1) / 2 > idx) ti--;
    const int tj = idx - ti * (ti + 1) / 2;
    const int i0 = ti << 7, j0 = tj << 7;

    const int tid = threadIdx.x;
    const int ty = tid >> 4, tx = tid & 15;
    const int lrow = tid >> 1, lc4 = (tid & 1) << 2;
    const int kvh = h >> 2;

    const float* Ap = g_pr + (size_t)(i0 + lrow) * NOUT + CQ + h * DH + lc4;
    const float* Bp = g_pr + (size_t)(j0 + lrow) * NOUT + CK + kvh * DH + lc4;

    float acc[8][8];
#pragma unroll
    for (int i = 0; i < 8; i++)
#pragma unroll
        for (int j = 0; j < 8; j++) acc[i][j] = 0.f;

    for (int k0 = 0; k0 < DH; k0 += 8) {
        float4 av = *(const float4*)(Ap + k0);
        float4 bv = *(const float4*)(Bp + k0);
        As[lc4+0][lrow] = av.x; As[lc4+1][lrow] = av.y;
        As[lc4+2][lrow] = av.z; As[lc4+3][lrow] = av.w;
        Bs[lc4+0][lrow] = bv.x; Bs[lc4+1][lrow] = bv.y;
        Bs[lc4+2][lrow] = bv.z; Bs[lc4+3][lrow] = bv.w;
        __syncthreads();
#pragma unroll
        for (int kk = 0; kk < 8; kk++) {
            float4 a0 = *(const float4*)&As[kk][ty*8];
            float4 a1 = *(const float4*)&As[kk][ty*8+4];
            float4 b0 = *(const float4*)&Bs[kk][tx*8];
            float4 b1 = *(const float4*)&Bs[kk][tx*8+4];
            float a[8] = {a0.x,a0.y,a0.z,a0.w,a1.x,a1.y,a1.z,a1.w};
            float b[8] = {b0.x,b0.y,b0.z,b0.w,b1.x,b1.y,b1.z,b1.w};
#pragma unroll
            for (int i = 0; i < 8; i++)
#pragma unroll
                for (int j = 0; j < 8; j++)
                    acc[i][j] = fmaf(a[i], b[j], acc[i][j]);
        }
        __syncthreads();
    }

    const float scale = 0.08838834764831845f;
#pragma unroll
    for (int i = 0; i < 8; i++)
#pragma unroll
        for (int j = 0; j < 8; j++) acc[i][j] *= scale;

    if (h < NHG) {
        const float gs  = gscale[h];
        const int   np  = (h < NSYM) ? 2 : 1;
        const float wgs = gs * ((h < NSYM) ? 0.5f : 1.f);
        for (int p = 0; p < np; p++) {
            const int rqr = p ? j0 : i0;
            const int rkr = p ? i0 : j0;
#pragma unroll
            for (int it = 0; it < 4; it++) {
                int lin = tid + it * 256;
                int row = lin >> 3;
                int c4  = (lin & 7) << 2;
                float4 a = *(const float4*)(g_pr + (size_t)(rqr + row) * NOUT + CRQ + h * RDIM + c4);
                float4 b = *(const float4*)(g_pr + (size_t)(rkr + row) * NOUT + CRK + h * RDIM + c4);
                Rq_s[row][c4+0]=a.x; Rq_s[row][c4+1]=a.y; Rq_s[row][c4+2]=a.z; Rq_s[row][c4+3]=a.w;
                Rk_s[row][c4+0]=b.x; Rk_s[row][c4+1]=b.y; Rk_s[row][c4+2]=b.z; Rk_s[row][c4+3]=b.w;
            }
            __syncthreads();
#pragma unroll 8
            for (int r = 0; r < RDIM; r++) {
                float a[8], b[8];
                if (p == 0) {
#pragma unroll
                    for (int i = 0; i < 8; i++) a[i] = Rq_s[ty*8+i][r] * wgs;
#pragma unroll
                    for (int j = 0; j < 8; j++) b[j] = Rk_s[tx*8+j][r];
                } else {
#pragma unroll
                    for (int i = 0; i < 8; i++) a[i] = Rk_s[ty*8+i][r] * wgs;
#pragma unroll
                    for (int j = 0; j < 8; j++) b[j] = Rq_s[tx*8+j][r];
                }
#pragma unroll
                for (int i = 0; i < 8; i++)
#pragma unroll
                    for (int j = 0; j < 8; j++)
                        acc[i][j] = fmaf(a[i], b[j], acc[i][j]);
            }
            __syncthreads();
        }
    }

#pragma unroll
    for (int i = 0; i < 8; i++) {
        const int gi = i0 + ty*8 + i;
        float* Cp = g_sc + ((size_t)h * SDIM + gi) * SDIM + j0 + tx*8;
#pragma unroll
        for (int j = 0; j < 8; j++) {
            const int gj = j0 + tx*8 + j;
            Cp[j] = (gj <= gi) ? acc[i][j] : 0.f;
        }
    }
}

// ---------------- Row softmax ----------------
__global__ __launch_bounds__(256) void softmax_kernel()
{
    const int i = blockIdx.x, h = blockIdx.y;
    const int len = i + 1;
    float* row = g_sc + ((size_t)h * SDIM + i) * SDIM;
    __shared__ float buf[SDIM];
    __shared__ float red[8];
    const int tid = threadIdx.x;

    float m = -3.4e38f;
    for (int j = tid; j < len; j += 256) { float v = row[j]; buf[j] = v; m = fmaxf(m, v); }
#pragma unroll
    for (int o = 16; o; o >>= 1) m = fmaxf(m, __shfl_xor_sync(0xffffffffu, m, o));
    if ((tid & 31) == 0) red[tid >> 5] = m;
    __syncthreads();
    m = red[0];
#pragma unroll
    for (int q = 1; q < 8; q++) m = fmaxf(m, red[q]);
    __syncthreads();

    float sum = 0.f;
    for (int j = tid; j < len; j += 256) { float e = __expf(buf[j] - m); buf[j] = e; sum += e; }
#pragma unroll
    for (int o = 16; o; o >>= 1) sum += __shfl_xor_sync(0xffffffffu, sum, o);
    if ((tid & 31) == 0) red[tid >> 5] = sum;
    __syncthreads();
    sum = red[0] + red[1] + red[2] + red[3] + red[4] + red[5] + red[6] + red[7];
    const float inv = 1.f / sum;
    for (int j = tid; j < len; j += 256) row[j] = buf[j] * inv;
}

// ---------------- AV ----------------
__global__ __launch_bounds__(256) void gemm_av()
{
    __shared__ float As[8][128];
    __shared__ float Bs[8][128];
    const int h = blockIdx.y;
    const int m0 = blockIdx.x << 7;
    const int kvh = h >> 2;
    const int tid = threadIdx.x;
    const int ty = tid >> 4, tx = tid & 15;
    const int lrow = tid >> 1, lc4 = (tid & 1) << 2;
    const int brow = tid >> 5, bc4 = (tid & 31) << 2;

    const float* Ap = g_sc + ((size_t)h * SDIM + m0 + lrow) * SDIM + lc4;
    const float* Bp = g_pr + CV + kvh * DH + bc4;

    float acc[8][8];
#pragma unroll
    for (int i = 0; i < 8; i++)
#pragma unroll
        for (int j = 0; j < 8; j++) acc[i][j] = 0.f;

    const int kmax = m0 + 128;
    for (int k0 = 0; k0 < kmax; k0 += 8) {
        float4 av = *(const float4*)(Ap + k0);
        float4 bv = *(const float4*)(Bp + (size_t)(k0 + brow) * NOUT);
        As[lc4+0][lrow] = av.x; As[lc4+1][lrow] = av.y;
        As[lc4+2][lrow] = av.z; As[lc4+3][lrow] = av.w;
        *(float4*)&Bs[brow][bc4] = bv;
        __syncthreads();
#pragma unroll
        for (int kk = 0; kk < 8; kk++) {
            float4 a0 = *(const float4*)&As[kk][ty*8];
            float4 a1 = *(const float4*)&As[kk][ty*8+4];
            float4 b0 = *(const float4*)&Bs[kk][tx*8];
            float4 b1 = *(const float4*)&Bs[kk][tx*8+4];
            float a[8] = {a0.x,a0.y,a0.z,a0.w,a1.x,a1.y,a1.z,a1.w};
            float b[8] = {b0.x,b0.y,b0.z,b0.w,b1.x,b1.y,b1.z,b1.w};
#pragma unroll
            for (int i = 0; i < 8; i++)
#pragma unroll
                for (int j = 0; j < 8; j++)
                    acc[i][j] = fmaf(a[i], b[j], acc[i][j]);
        }
        __syncthreads();
    }
#pragma unroll
    for (int i = 0; i < 8; i++) {
        float* Cp = g_ao + (size_t)(m0 + ty*8 + i) * EDIM + h * DH + tx*8;
        *(float4*)(Cp)   = make_float4(acc[i][0],acc[i][1],acc[i][2],acc[i][3]);
        *(float4*)(Cp+4) = make_float4(acc[i][4],acc[i][5],acc[i][6],acc[i][7]);
    }
}

// ---------------- Host ----------------
extern "C" void kernel_launch(void* const* d_in, const int* in_sizes, int n_in,
                              void* d_out, int out_size)
{
    const float* x   = (const float*)d_in[0];
    const float* Wq  = (const float*)d_in[1];
    const float* Wk  = (const float*)d_in[2];
    const float* Wv  = (const float*)d_in[3];
    const float* Wo  = (const float*)d_in[4];
    const float* qnw = (const float*)d_in[5];
    const float* knw = (const float*)d_in[6];
    const float* Wrq = (const float*)d_in[7];
    const float* Wrk = (const float*)d_in[8];
    const float* gsc = (const float*)d_in[9];
    float* out = (float*)d_out;

    float *pr, *ao;
    __nv_bfloat16 *x3, *ao3, *w3, *wo3;
    cudaGetSymbolAddress((void**)&pr,  g_pr);
    cudaGetSymbolAddress((void**)&ao,  g_ao);
    cudaGetSymbolAddress((void**)&x3,  g_x3);
    cudaGetSymbolAddress((void**)&ao3, g_ao3);
    cudaGetSymbolAddress((void**)&w3,  g_w3);
    cudaGetSymbolAddress((void**)&wo3, g_wo3);

    cudaFuncSetAttribute(gemm_bf16, cudaFuncAttributeMaxDynamicSharedMemorySize, 98304);

    // Folds: x (A side); weights concatenated into g_w3 rows (B side)
    split_pair<<<SDIM*EDIM/512, 256>>>(x,   x3,                      SDIM*EDIM/2, 0);
    split_pair<<<EDIM*EDIM/512, 256>>>(Wq,  w3 + (size_t)CQ  * KP,   EDIM*EDIM/2, 1);
    split_pair<<<512*EDIM/512,  256>>>(Wk,  w3 + (size_t)CK  * KP,   512*EDIM/2,  1);
    split_pair<<<512*EDIM/512,  256>>>(Wv,  w3 + (size_t)CV  * KP,   512*EDIM/2,  1);
    split_pair<<<384*EDIM/512,  256>>>(Wrq, w3 + (size_t)CRQ * KP,   384*EDIM/2,  1);
    split_pair<<<384*EDIM/512,  256>>>(Wrk, w3 + (size_t)CRK * KP,   384*EDIM/2,  1);
    split_pair<<<EDIM*EDIM/512, 256>>>(Wo,  wo3,                     EDIM*EDIM/2, 1);

    // One merged projection GEMM: [x] @ [Wq|Wk|Wv|Wrq|Wrk]^T
    gemm_bf16<<<dim3(NOUT/128, 16), 256, 98304>>>(x3, w3, pr, NOUT, KP);

    norm_rope<<<dim3(SDIM, NH),  128>>>(pr + CQ, qnw);
    norm_rope<<<dim3(SDIM, NKV), 128>>>(pr + CK, knw);

    scores_kernel<<<dim3(136, NH), 256>>>(gsc);
    softmax_kernel<<<dim3(SDIM, NH), 256>>>();
    gemm_av<<<dim3(16, NH), 256>>>();

    split_pair<<<SDIM*EDIM/512, 256>>>(ao, ao3, SDIM*EDIM/2, 0);
    gemm_bf16<<<dim3(16, 16), 256, 98304>>>(ao3, wo3, out, EDIM, KP);
}

// round 6
// speedup vs baseline: 3.6743x; 1.6008x over previous
#include <cuda_runtime.h>
#include <cuda_bf16.h>
#include <math.h>
#include <stdint.h>

#define SDIM 2048
#define EDIM 2048
#define NH   16
#define NKV  4
#define DH   128
#define NHG  12
#define RDIM 32
#define NSYM 4
#define KP   (3*EDIM)   // 6144 folded K for projections
#define NOUT 3840
#define CQ   0
#define CK   2048
#define CV   2560
#define CRQ  3072
#define CRK  3456
#define KQ   448        // folded q/k (384) + bias cols (64)
#define KA   (3*SDIM)   // 6144 folded attn/v K

static __device__ float g_pr[SDIM*NOUT];
static __device__ float g_sc[(size_t)NH*SDIM*SDIM];
static __device__ float g_ao[SDIM*EDIM];
static __device__ __nv_bfloat16 g_x3 [SDIM*KP];
static __device__ __nv_bfloat16 g_ao3[SDIM*KP];
static __device__ __nv_bfloat16 g_w3 [(size_t)NOUT*KP];
static __device__ __nv_bfloat16 g_wo3[(size_t)EDIM*KP];
static __device__ __nv_bfloat16 g_qa [(size_t)NH*SDIM*KQ];
static __device__ __nv_bfloat16 g_kb [(size_t)NH*SDIM*KQ];
static __device__ __nv_bfloat16 g_vt [(size_t)NKV*DH*KA];
static __device__ __nv_bfloat16 g_at [(size_t)NH*SDIM*KA];   // folded attn

// ---------------- PTX helpers ----------------
__device__ __forceinline__ uint32_t smem_u32(const void* p) {
    uint32_t a;
    asm("{ .reg .u64 t; cvta.to.shared.u64 t, %1; cvt.u32.u64 %0, t; }" : "=r"(a) : "l"(p));
    return a;
}
__device__ __forceinline__ void cpa16(uint32_t d, const void* g) {
    asm volatile("cp.async.cg.shared.global [%0], [%1], 16;" :: "r"(d), "l"(g));
}
__device__ __forceinline__ void cp_commit() { asm volatile("cp.async.commit_group;" ::: "memory"); }
template<int N> __device__ __forceinline__ void cp_wait() {
    asm volatile("cp.async.wait_group %0;" :: "n"(N) : "memory");
}
__device__ __forceinline__ void ldm_x4(uint32_t& r0, uint32_t& r1, uint32_t& r2, uint32_t& r3,
                                       uint32_t addr) {
    asm volatile("ldmatrix.sync.aligned.m8n8.x4.shared.b16 {%0,%1,%2,%3}, [%4];"
                 : "=r"(r0), "=r"(r1), "=r"(r2), "=r"(r3) : "r"(addr));
}
__device__ __forceinline__ void mma_bf16(float* d, const uint32_t* a, const uint32_t* b) {
    asm volatile("mma.sync.aligned.m16n8k16.row.col.f32.bf16.bf16.f32 "
                 "{%0,%1,%2,%3}, {%4,%5,%6,%7}, {%8,%9}, {%0,%1,%2,%3};"
                 : "+f"(d[0]), "+f"(d[1]), "+f"(d[2]), "+f"(d[3])
                 : "r"(a[0]), "r"(a[1]), "r"(a[2]), "r"(a[3]), "r"(b[0]), "r"(b[1]));
}
__device__ __forceinline__ void fold2(float v, uint32_t& H, uint32_t& L) {
    __nv_bfloat16 h = __float2bfloat16(v);
    __nv_bfloat16 l = __float2bfloat16(v - __bfloat162float(h));
    H = __bfloat16_as_ushort(h); L = __bfloat16_as_ushort(l);
}

// ---------------- bf16x2 K-fold split ----------------
__global__ __launch_bounds__(256) void split_pair(
    const float* __restrict__ s, __nv_bfloat16* __restrict__ d, int npairs, int isB)
{
    int i = blockIdx.x * 256 + threadIdx.x;
    if (i >= npairs) return;
    float2 v = ((const float2*)s)[i];
    uint32_t H0, L0, H1, L1;
    fold2(v.x, H0, L0); fold2(v.y, H1, L1);
    uint32_t w0, w1, w2;
    if (!isB) { w0 = H0 | (H0 << 16); w1 = L0 | (H1 << 16); w2 = H1 | (L1 << 16); }
    else      { w0 = H0 | (L0 << 16); w1 = H0 | (H1 << 16); w2 = L1 | (H1 << 16); }
    uint32_t* o = (uint32_t*)d + 3 * (size_t)i;
    o[0] = w0; o[1] = w1; o[2] = w2;
}

// ---------------- shared GEMM machinery ----------------
#define GEMM_PREAMBLE                                                           \
    extern __shared__ __align__(1024) char dsm[];                               \
    const uint32_t sb = smem_u32(dsm);                                          \
    const int tid = threadIdx.x;                                                \
    const int l = tid & 31, wid = tid >> 5;                                     \
    const int cch = tid & 7;                                                    \
    const int akh = (l >> 4);                                                   \
    const int bkh = (l >> 3) & 1;                                               \
    const int lsw = l & 7;

#define LOAD128(base, P, ld, step) do {                                         \
    const __nv_bfloat16* G = (P) + (size_t)(step) * 64;                         \
    _Pragma("unroll")                                                           \
    for (int it = 0; it < 4; it++) {                                            \
        int row = (tid >> 3) + 32 * it;                                         \
        uint32_t sw = row * 128u + 16u * (cch ^ (row & 7));                     \
        cpa16((base) + sw, G + (size_t)row * (ld) + cch * 8);                   \
    } } while (0)

#define LOAD64(base, P, ld, step) do {                                          \
    const __nv_bfloat16* G = (P) + (size_t)(step) * 64;                         \
    _Pragma("unroll")                                                           \
    for (int it = 0; it < 2; it++) {                                            \
        int row = (tid >> 3) + 32 * it;                                         \
        uint32_t sw = row * 128u + 16u * (cch ^ (row & 7));                     \
        cpa16((base) + sw, G + (size_t)row * (ld) + cch * 8);                   \
    } } while (0)

// ---------------- bf16 NT GEMM, 128x128 tile (proj / Wo) ----------------
__global__ __launch_bounds__(256) void gemm_bf16(
    const __nv_bfloat16* __restrict__ A, const __nv_bfloat16* __restrict__ B,
    float* __restrict__ C, int ldc, int kp)
{
    GEMM_PREAMBLE
    const int wm = wid & 1, wn = wid >> 1;
    const int m0 = blockIdx.y << 7, n0 = blockIdx.x << 7;
    const int steps = kp >> 6;
    const __nv_bfloat16* Ab_ = A + (size_t)m0 * kp;
    const __nv_bfloat16* Bb_ = B + (size_t)n0 * kp;

    float acc[4][4][4];
#pragma unroll
    for (int i = 0; i < 4; i++)
#pragma unroll
        for (int j = 0; j < 4; j++)
#pragma unroll
            for (int r = 0; r < 4; r++) acc[i][j][r] = 0.f;

    const int ar = wm * 64 + (l & 7) + (l & 8);
    const int br = wn * 32 + (l & 7) + 8 * (l >> 4);

    LOAD128(sb, Ab_, kp, 0); LOAD128(sb + 16384u, Bb_, kp, 0); cp_commit();
    if (steps > 1) { LOAD128(sb + 32768u, Ab_, kp, 1); LOAD128(sb + 49152u, Bb_, kp, 1); }
    cp_commit();

    for (int s = 0; s < steps; s++) {
        if (s + 2 < steps) {
            uint32_t b2 = sb + ((s + 2) % 3) * 32768u;
            LOAD128(b2, Ab_, kp, s + 2); LOAD128(b2 + 16384u, Bb_, kp, s + 2);
        }
        cp_commit(); cp_wait<2>(); __syncthreads();
        const uint32_t Ab = sb + (s % 3) * 32768u;
        const uint32_t Bb = Ab + 16384u;
#pragma unroll
        for (int kk = 0; kk < 4; kk++) {
            uint32_t af[4][4], bf[4][2];
#pragma unroll
            for (int tm = 0; tm < 4; tm++)
                ldm_x4(af[tm][0], af[tm][1], af[tm][2], af[tm][3],
                       Ab + (uint32_t)(ar + tm * 16) * 128u + 16u * (((kk << 1) + akh) ^ lsw));
#pragma unroll
            for (int np = 0; np < 2; np++) {
                uint32_t r0, r1, r2, r3;
                ldm_x4(r0, r1, r2, r3,
                       Bb + (uint32_t)(br + np * 16) * 128u + 16u * (((kk << 1) + bkh) ^ lsw));
                bf[2*np][0] = r0; bf[2*np][1] = r1; bf[2*np+1][0] = r2; bf[2*np+1][1] = r3;
            }
#pragma unroll
            for (int tm = 0; tm < 4; tm++)
#pragma unroll
                for (int tn = 0; tn < 4; tn++) mma_bf16(acc[tm][tn], af[tm], bf[tn]);
        }
        __syncthreads();
    }
    const int er = m0 + wm * 64 + (l >> 2);
    const int ec = n0 + wn * 32 + 2 * (l & 3);
#pragma unroll
    for (int tm = 0; tm < 4; tm++)
#pragma unroll
        for (int tn = 0; tn < 4; tn++) {
            float* p0 = C + (size_t)(er + tm * 16) * ldc + ec + tn * 8;
            float* p1 = C + (size_t)(er + tm * 16 + 8) * ldc + ec + tn * 8;
            *(float2*)p0 = make_float2(acc[tm][tn][0], acc[tm][tn][1]);
            *(float2*)p1 = make_float2(acc[tm][tn][2], acc[tm][tn][3]);
        }
}

// ---------------- scores on tensor cores (+fused bias, causal mask) ----------
__global__ __launch_bounds__(256) void scores_mma()
{
    GEMM_PREAMBLE
    const int wm = wid & 1, wn = wid >> 1;
    const int h = blockIdx.y, idx = blockIdx.x;
    int ti = (int)((sqrtf(8.f * idx + 1.f) - 1.f) * 0.5f);
    while ((ti + 1) * (ti + 2) / 2 <= idx) ti++;
    while (ti * (ti + 1) / 2 > idx) ti--;
    const int tj = idx - ti * (ti + 1) / 2;
    const int i0 = ti << 7, j0 = tj << 7;
    const __nv_bfloat16* Ab_ = g_qa + ((size_t)h * SDIM + i0) * KQ;
    const __nv_bfloat16* Bb_ = g_kb + ((size_t)h * SDIM + j0) * KQ;
    const int steps = KQ >> 6;   // 7

    float acc[4][4][4];
#pragma unroll
    for (int i = 0; i < 4; i++)
#pragma unroll
        for (int j = 0; j < 4; j++)
#pragma unroll
            for (int r = 0; r < 4; r++) acc[i][j][r] = 0.f;
    const int ar = wm * 64 + (l & 7) + (l & 8);
    const int br = wn * 32 + (l & 7) + 8 * (l >> 4);

    LOAD128(sb, Ab_, KQ, 0); LOAD128(sb + 16384u, Bb_, KQ, 0); cp_commit();
    LOAD128(sb + 32768u, Ab_, KQ, 1); LOAD128(sb + 49152u, Bb_, KQ, 1); cp_commit();

    for (int s = 0; s < steps; s++) {
        if (s + 2 < steps) {
            uint32_t b2 = sb + ((s + 2) % 3) * 32768u;
            LOAD128(b2, Ab_, KQ, s + 2); LOAD128(b2 + 16384u, Bb_, KQ, s + 2);
        }
        cp_commit(); cp_wait<2>(); __syncthreads();
        const uint32_t Ab = sb + (s % 3) * 32768u;
        const uint32_t Bb = Ab + 16384u;
#pragma unroll
        for (int kk = 0; kk < 4; kk++) {
            uint32_t af[4][4], bf[4][2];
#pragma unroll
            for (int tm = 0; tm < 4; tm++)
                ldm_x4(af[tm][0], af[tm][1], af[tm][2], af[tm][3],
                       Ab + (uint32_t)(ar + tm * 16) * 128u + 16u * (((kk << 1) + akh) ^ lsw));
#pragma unroll
            for (int np = 0; np < 2; np++) {
                uint32_t r0, r1, r2, r3;
                ldm_x4(r0, r1, r2, r3,
                       Bb + (uint32_t)(br + np * 16) * 128u + 16u * (((kk << 1) + bkh) ^ lsw));
                bf[2*np][0] = r0; bf[2*np][1] = r1; bf[2*np+1][0] = r2; bf[2*np+1][1] = r3;
            }
#pragma unroll
            for (int tm = 0; tm < 4; tm++)
#pragma unroll
                for (int tn = 0; tn < 4; tn++) mma_bf16(acc[tm][tn], af[tm], bf[tn]);
        }
        __syncthreads();
    }
    const int er = i0 + wm * 64 + (l >> 2);
    const int ec = j0 + wn * 32 + 2 * (l & 3);
#pragma unroll
    for (int tm = 0; tm < 4; tm++)
#pragma unroll
        for (int tn = 0; tn < 4; tn++) {
            int r0 = er + tm * 16, r1 = r0 + 8, c = ec + tn * 8;
            float* p0 = g_sc + ((size_t)h * SDIM + r0) * SDIM + c;
            float* p1 = g_sc + ((size_t)h * SDIM + r1) * SDIM + c;
            *(float2*)p0 = make_float2(c     <= r0 ? acc[tm][tn][0] : 0.f,
                                       c + 1 <= r0 ? acc[tm][tn][1] : 0.f);
            *(float2*)p1 = make_float2(c     <= r1 ? acc[tm][tn][2] : 0.f,
                                       c + 1 <= r1 ? acc[tm][tn][3] : 0.f);
        }
}

// ---------------- AV on tensor cores (balanced pairs) ----------------
__global__ __launch_bounds__(256) void av_mma()
{
    GEMM_PREAMBLE
    const int wm = wid & 1, wn = wid >> 1;
    const int h = blockIdx.y;
    const __nv_bfloat16* Bb_ = g_vt + (size_t)(h >> 2) * DH * KA;

    for (int half = 0; half < 2; half++) {
        const int mt = half ? 31 - (int)blockIdx.x : (int)blockIdx.x;
        const int m0 = mt << 6;
        const int steps = 3 * (mt + 1);
        const __nv_bfloat16* Ab_ = g_at + ((size_t)h * SDIM + m0) * KA;

        float acc[2][4][4];
#pragma unroll
        for (int i = 0; i < 2; i++)
#pragma unroll
            for (int j = 0; j < 4; j++)
#pragma unroll
                for (int r = 0; r < 4; r++) acc[i][j][r] = 0.f;
        const int ar = wm * 32 + (l & 7) + (l & 8);
        const int br = wn * 32 + (l & 7) + 8 * (l >> 4);

        LOAD64(sb, Ab_, KA, 0); LOAD128(sb + 8192u, Bb_, KA, 0); cp_commit();
        LOAD64(sb + 24576u, Ab_, KA, 1); LOAD128(sb + 32768u, Bb_, KA, 1); cp_commit();

        for (int s = 0; s < steps; s++) {
            if (s + 2 < steps) {
                uint32_t b2 = sb + ((s + 2) % 3) * 24576u;
                LOAD64(b2, Ab_, KA, s + 2); LOAD128(b2 + 8192u, Bb_, KA, s + 2);
            }
            cp_commit(); cp_wait<2>(); __syncthreads();
            const uint32_t Ab = sb + (s % 3) * 24576u;
            const uint32_t Bb = Ab + 8192u;
#pragma unroll
            for (int kk = 0; kk < 4; kk++) {
                uint32_t af[2][4], bf[4][2];
#pragma unroll
                for (int tm = 0; tm < 2; tm++)
                    ldm_x4(af[tm][0], af[tm][1], af[tm][2], af[tm][3],
                           Ab + (uint32_t)(ar + tm * 16) * 128u + 16u * (((kk << 1) + akh) ^ lsw));
#pragma unroll
                for (int np = 0; np < 2; np++) {
                    uint32_t r0, r1, r2, r3;
                    ldm_x4(r0, r1, r2, r3,
                           Bb + (uint32_t)(br + np * 16) * 128u + 16u * (((kk << 1) + bkh) ^ lsw));
                    bf[2*np][0] = r0; bf[2*np][1] = r1; bf[2*np+1][0] = r2; bf[2*np+1][1] = r3;
                }
#pragma unroll
                for (int tm = 0; tm < 2; tm++)
#pragma unroll
                    for (int tn = 0; tn < 4; tn++) mma_bf16(acc[tm][tn], af[tm], bf[tn]);
            }
            __syncthreads();
        }
        const int er = m0 + wm * 32 + (l >> 2);
        const int ec = h * DH + wn * 32 + 2 * (l & 3);
#pragma unroll
        for (int tm = 0; tm < 2; tm++)
#pragma unroll
            for (int tn = 0; tn < 4; tn++) {
                float* p0 = g_ao + (size_t)(er + tm * 16) * EDIM + ec + tn * 8;
                float* p1 = g_ao + (size_t)(er + tm * 16 + 8) * EDIM + ec + tn * 8;
                *(float2*)p0 = make_float2(acc[tm][tn][0], acc[tm][tn][1]);
                *(float2*)p1 = make_float2(acc[tm][tn][2], acc[tm][tn][3]);
            }
        __syncthreads();
    }
}

// ---------------- RMSNorm + RoPE ----------------
__global__ __launch_bounds__(128) void norm_rope(
    float* __restrict__ buf, const float* __restrict__ w)
{
    const int s = blockIdx.x, h = blockIdx.y, d = threadIdx.x;
    float* p = buf + (size_t)s * NOUT + h * DH;
    float v = p[d];
    float ss = v * v;
#pragma unroll
    for (int o = 16; o; o >>= 1) ss += __shfl_xor_sync(0xffffffffu, ss, o);
    __shared__ float r4[4];
    __shared__ float sh[DH];
    if ((d & 31) == 0) r4[d >> 5] = ss;
    __syncthreads();
    float tot = r4[0] + r4[1] + r4[2] + r4[3];
    float nv = v * rsqrtf(tot * (1.f / DH) + 1e-6f) * w[d];
    sh[d] = nv;
    __syncthreads();
    const int dm = d & 63;
    float f = 1.f / powf(10000.f, (float)(2 * dm) * (1.f / DH));
    float cs, sn;
    sincosf((float)s * f, &sn, &cs);
    float rot = (d < 64) ? -sh[d + 64] : sh[d - 64];
    p[d] = nv * cs + rot * sn;
}

// ---------------- fill qa / kb (folded q,k + bias columns) ----------------
__global__ __launch_bounds__(128) void fill_qa(const float* __restrict__ gscale)
{
    const int s = blockIdx.x, h = blockIdx.y, d = threadIdx.x;
    __nv_bfloat16* row = g_qa + ((size_t)h * SDIM + s) * KQ;
    float qs = g_pr[(size_t)s * NOUT + CQ + h * DH + d] * 0.08838834764831845f;
    uint32_t H, L; fold2(qs, H, L);
    row[3*d]   = __ushort_as_bfloat16((unsigned short)H);
    row[3*d+1] = __ushort_as_bfloat16((unsigned short)H);
    row[3*d+2] = __ushort_as_bfloat16((unsigned short)L);
    if (d < 32) {
        float v = 0.f;
        if (h < NHG) {
            float wgs = gscale[h] * (h < NSYM ? 0.5f : 1.f);
            v = wgs * g_pr[(size_t)s * NOUT + CRQ + h * RDIM + d];
        }
        row[384 + d] = __float2bfloat16(v);
    } else if (d < 64) {
        int r = d - 32;
        float v = 0.f;
        if (h < NSYM) {
            float wgs = gscale[h] * 0.5f;
            v = wgs * g_pr[(size_t)s * NOUT + CRK + h * RDIM + r];
        }
        row[416 + r] = __float2bfloat16(v);
    }
}
__global__ __launch_bounds__(128) void fill_kb()
{
    const int s = blockIdx.x, h = blockIdx.y, d = threadIdx.x;
    __nv_bfloat16* row = g_kb + ((size_t)h * SDIM + s) * KQ;
    float kv = g_pr[(size_t)s * NOUT + CK + (h >> 2) * DH + d];
    uint32_t H, L; fold2(kv, H, L);
    row[3*d]   = __ushort_as_bfloat16((unsigned short)H);
    row[3*d+1] = __ushort_as_bfloat16((unsigned short)L);
    row[3*d+2] = __ushort_as_bfloat16((unsigned short)H);
    if (d < 32) {
        float v = (h < NHG) ? g_pr[(size_t)s * NOUT + CRK + h * RDIM + d] : 0.f;
        row[384 + d] = __float2bfloat16(v);
    } else if (d < 64) {
        int r = d - 32;
        float v = (h < NSYM) ? g_pr[(size_t)s * NOUT + CRQ + h * RDIM + r] : 0.f;
        row[416 + r] = __float2bfloat16(v);
    }
}
// ---------------- fill vt (transpose + B-side fold) ----------------
__global__ __launch_bounds__(128) void fill_vt()
{
    const int jb = blockIdx.x, kvh = blockIdx.y, d = threadIdx.x;
    __nv_bfloat16* row = g_vt + ((size_t)kvh * DH + d) * KA;
    for (int jj = 0; jj < 128; jj++) {
        int j = jb * 128 + jj;
        float v = g_pr[(size_t)j * NOUT + CV + kvh * DH + d];
        uint32_t H, L; fold2(v, H, L);
        row[3*j]   = __ushort_as_bfloat16((unsigned short)H);
        row[3*j+1] = __ushort_as_bfloat16((unsigned short)L);
        row[3*j+2] = __ushort_as_bfloat16((unsigned short)H);
    }
}

// ---------------- softmax: read scores fp32, write folded attn ----------------
__global__ __launch_bounds__(256) void softmax_kernel()
{
    const int i = blockIdx.x, h = blockIdx.y;
    const int len = i + 1;
    const int lenp = (len + 127) & ~127;
    const float* row = g_sc + ((size_t)h * SDIM + i) * SDIM;
    __shared__ float buf[SDIM];
    __shared__ float red[8];
    const int tid = threadIdx.x;

    float m = -3.4e38f;
    for (int j = tid; j < len; j += 256) { float v = row[j]; buf[j] = v; m = fmaxf(m, v); }
#pragma unroll
    for (int o = 16; o; o >>= 1) m = fmaxf(m, __shfl_xor_sync(0xffffffffu, m, o));
    if ((tid & 31) == 0) red[tid >> 5] = m;
    __syncthreads();
    m = red[0];
#pragma unroll
    for (int q = 1; q < 8; q++) m = fmaxf(m, red[q]);
    __syncthreads();

    float sum = 0.f;
    for (int j = tid; j < len; j += 256) { float e = __expf(buf[j] - m); buf[j] = e; sum += e; }
#pragma unroll
    for (int o = 16; o; o >>= 1) sum += __shfl_xor_sync(0xffffffffu, sum, o);
    if ((tid & 31) == 0) red[tid >> 5] = sum;
    __syncthreads();
    sum = red[0] + red[1] + red[2] + red[3] + red[4] + red[5] + red[6] + red[7];
    const float inv = 1.f / sum;
    __syncthreads();

    uint32_t* orow = (uint32_t*)g_at + ((size_t)h * SDIM + i) * (KA / 2);
    for (int j2 = tid; j2 < (lenp >> 1); j2 += 256) {
        int j0 = 2 * j2;
        float a0 = (j0 < len)     ? buf[j0] * inv     : 0.f;
        float a1 = (j0 + 1 < len) ? buf[j0 + 1] * inv : 0.f;
        uint32_t H0, L0, H1, L1;
        fold2(a0, H0, L0); fold2(a1, H1, L1);
        orow[3*j2]   = H0 | (H0 << 16);
        orow[3*j2+1] = L0 | (H1 << 16);
        orow[3*j2+2] = H1 | (L1 << 16);
    }
}

// ---------------- Host ----------------
extern "C" void kernel_launch(void* const* d_in, const int* in_sizes, int n_in,
                              void* d_out, int out_size)
{
    const float* x   = (const float*)d_in[0];
    const float* Wq  = (const float*)d_in[1];
    const float* Wk  = (const float*)d_in[2];
    const float* Wv  = (const float*)d_in[3];
    const float* Wo  = (const float*)d_in[4];
    const float* qnw = (const float*)d_in[5];
    const float* knw = (const float*)d_in[6];
    const float* Wrq = (const float*)d_in[7];
    const float* Wrk = (const float*)d_in[8];
    const float* gsc = (const float*)d_in[9];
    float* out = (float*)d_out;

    float *pr, *ao;
    __nv_bfloat16 *x3, *ao3, *w3, *wo3;
    cudaGetSymbolAddress((void**)&pr,  g_pr);
    cudaGetSymbolAddress((void**)&ao,  g_ao);
    cudaGetSymbolAddress((void**)&x3,  g_x3);
    cudaGetSymbolAddress((void**)&ao3, g_ao3);
    cudaGetSymbolAddress((void**)&w3,  g_w3);
    cudaGetSymbolAddress((void**)&wo3, g_wo3);

    cudaFuncSetAttribute(gemm_bf16,  cudaFuncAttributeMaxDynamicSharedMemorySize, 98304);
    cudaFuncSetAttribute(scores_mma, cudaFuncAttributeMaxDynamicSharedMemorySize, 98304);
    cudaFuncSetAttribute(av_mma,     cudaFuncAttributeMaxDynamicSharedMemorySize, 73728);

    split_pair<<<SDIM*EDIM/512, 256>>>(x,   x3,                    SDIM*EDIM/2, 0);
    split_pair<<<EDIM*EDIM/512, 256>>>(Wq,  w3 + (size_t)CQ  * KP, EDIM*EDIM/2, 1);
    split_pair<<<512*EDIM/512,  256>>>(Wk,  w3 + (size_t)CK  * KP, 512*EDIM/2,  1);
    split_pair<<<512*EDIM/512,  256>>>(Wv,  w3 + (size_t)CV  * KP, 512*EDIM/2,  1);
    split_pair<<<384*EDIM/512,  256>>>(Wrq, w3 + (size_t)CRQ * KP, 384*EDIM/2,  1);
    split_pair<<<384*EDIM/512,  256>>>(Wrk, w3 + (size_t)CRK * KP, 384*EDIM/2,  1);
    split_pair<<<EDIM*EDIM/512, 256>>>(Wo,  wo3,                   EDIM*EDIM/2, 1);

    gemm_bf16<<<dim3(NOUT/128, 16), 256, 98304>>>(x3, w3, pr, NOUT, KP);

    norm_rope<<<dim3(SDIM, NH),  128>>>(pr + CQ, qnw);
    norm_rope<<<dim3(SDIM, NKV), 128>>>(pr + CK, knw);

    fill_qa<<<dim3(SDIM, NH), 128>>>(gsc);
    fill_kb<<<dim3(SDIM, NH), 128>>>();
    fill_vt<<<dim3(SDIM/128, NKV), 128>>>();

    scores_mma<<<dim3(136, NH), 256, 98304>>>();
    softmax_kernel<<<dim3(SDIM, NH), 256>>>();
    av_mma<<<dim3(16, NH), 256, 73728>>>();

    split_pair<<<SDIM*EDIM/512, 256>>>(ao, ao3, SDIM*EDIM/2, 0);
    gemm_bf16<<<dim3(16, 16), 256, 98304>>>(ao3, wo3, out, EDIM, KP);
}

// round 7
// speedup vs baseline: 4.0380x; 1.0990x over previous
#include <cuda_runtime.h>
#include <cuda_bf16.h>
#include <math.h>
#include <stdint.h>

#define SDIM 2048
#define EDIM 2048
#define NH   16
#define NKV  4
#define DH   128
#define NHG  12
#define RDIM 32
#define NSYM 4
#define KP   (3*EDIM)
#define NOUT 3840
#define CQ   0
#define CK   2048
#define CV   2560
#define CRQ  3072
#define CRK  3456
#define KQ   448
#define KA   (3*SDIM)

static __device__ float g_pr[SDIM*NOUT];
static __device__ float g_sc[(size_t)NH*SDIM*SDIM];
static __device__ __nv_bfloat16 g_x3 [SDIM*KP];
static __device__ __nv_bfloat16 g_ao3[SDIM*KP];
static __device__ __nv_bfloat16 g_w3 [(size_t)NOUT*KP];
static __device__ __nv_bfloat16 g_wo3[(size_t)EDIM*KP];
static __device__ __nv_bfloat16 g_qa [(size_t)NH*SDIM*KQ];
static __device__ __nv_bfloat16 g_kb [(size_t)NH*SDIM*KQ];
static __device__ __nv_bfloat16 g_vt [(size_t)NKV*DH*KA];
static __device__ __nv_bfloat16 g_at [(size_t)NH*SDIM*KA];

// ---------------- PTX helpers ----------------
__device__ __forceinline__ uint32_t smem_u32(const void* p) {
    uint32_t a;
    asm("{ .reg .u64 t; cvta.to.shared.u64 t, %1; cvt.u32.u64 %0, t; }" : "=r"(a) : "l"(p));
    return a;
}
__device__ __forceinline__ void cpa16(uint32_t d, const void* g) {
    asm volatile("cp.async.cg.shared.global [%0], [%1], 16;" :: "r"(d), "l"(g));
}
__device__ __forceinline__ void cp_commit() { asm volatile("cp.async.commit_group;" ::: "memory"); }
template<int N> __device__ __forceinline__ void cp_wait() {
    asm volatile("cp.async.wait_group %0;" :: "n"(N) : "memory");
}
__device__ __forceinline__ void ldm_x4(uint32_t& r0, uint32_t& r1, uint32_t& r2, uint32_t& r3,
                                       uint32_t addr) {
    asm volatile("ldmatrix.sync.aligned.m8n8.x4.shared.b16 {%0,%1,%2,%3}, [%4];"
                 : "=r"(r0), "=r"(r1), "=r"(r2), "=r"(r3) : "r"(addr));
}
__device__ __forceinline__ void mma_bf16(float* d, const uint32_t* a, const uint32_t* b) {
    asm volatile("mma.sync.aligned.m16n8k16.row.col.f32.bf16.bf16.f32 "
                 "{%0,%1,%2,%3}, {%4,%5,%6,%7}, {%8,%9}, {%0,%1,%2,%3};"
                 : "+f"(d[0]), "+f"(d[1]), "+f"(d[2]), "+f"(d[3])
                 : "r"(a[0]), "r"(a[1]), "r"(a[2]), "r"(a[3]), "r"(b[0]), "r"(b[1]));
}
__device__ __forceinline__ void fold2(float v, uint32_t& H, uint32_t& L) {
    __nv_bfloat16 h = __float2bfloat16(v);
    __nv_bfloat16 l = __float2bfloat16(v - __bfloat162float(h));
    H = __bfloat16_as_ushort(h); L = __bfloat16_as_ushort(l);
}
__device__ __forceinline__ void split_body(const float* s, __nv_bfloat16* d, int i, int isB) {
    float2 v = ((const float2*)s)[i];
    uint32_t H0, L0, H1, L1;
    fold2(v.x, H0, L0); fold2(v.y, H1, L1);
    uint32_t w0, w1, w2;
    if (!isB) { w0 = H0 | (H0 << 16); w1 = L0 | (H1 << 16); w2 = H1 | (L1 << 16); }
    else      { w0 = H0 | (L0 << 16); w1 = H0 | (H1 << 16); w2 = L1 | (H1 << 16); }
    uint32_t* o = (uint32_t*)d + 3 * (size_t)i;
    o[0] = w0; o[1] = w1; o[2] = w2;
}

__global__ __launch_bounds__(256) void split_pair(
    const float* __restrict__ s, __nv_bfloat16* __restrict__ d, int npairs, int isB)
{
    int i = blockIdx.x * 256 + threadIdx.x;
    if (i < npairs) split_body(s, d, i, isB);
}
__global__ __launch_bounds__(256) void split2(
    const float* __restrict__ s1, __nv_bfloat16* __restrict__ d1, int n1,
    const float* __restrict__ s2, __nv_bfloat16* __restrict__ d2, int n2)
{
    int i = blockIdx.x * 256 + threadIdx.x;
    if (i < n1) split_body(s1, d1, i, 1);
    else if (i < n1 + n2) split_body(s2, d2, i - n1, 1);
}

// ---------------- shared GEMM machinery ----------------
#define GEMM_PREAMBLE                                                           \
    extern __shared__ __align__(1024) char dsm[];                               \
    const uint32_t sb = smem_u32(dsm);                                          \
    const int tid = threadIdx.x;                                                \
    const int l = tid & 31, wid = tid >> 5;                                     \
    const int cch = tid & 7;                                                    \
    const int akh = (l >> 4);                                                   \
    const int bkh = (l >> 3) & 1;                                               \
    const int lsw = l & 7;

#define LOAD128(base, P, ld, step) do {                                         \
    const __nv_bfloat16* G = (P) + (size_t)(step) * 64;                         \
    _Pragma("unroll")                                                           \
    for (int it = 0; it < 4; it++) {                                            \
        int row = (tid >> 3) + 32 * it;                                         \
        uint32_t sw = row * 128u + 16u * (cch ^ (row & 7));                     \
        cpa16((base) + sw, G + (size_t)row * (ld) + cch * 8);                   \
    } } while (0)

#define LOAD64(base, P, ld, step) do {                                          \
    const __nv_bfloat16* G = (P) + (size_t)(step) * 64;                         \
    _Pragma("unroll")                                                           \
    for (int it = 0; it < 2; it++) {                                            \
        int row = (tid >> 3) + 32 * it;                                         \
        uint32_t sw = row * 128u + 16u * (cch ^ (row & 7));                     \
        cpa16((base) + sw, G + (size_t)row * (ld) + cch * 8);                   \
    } } while (0)

#define INNER_128(Ab, Bb)                                                       \
    _Pragma("unroll")                                                           \
    for (int kk = 0; kk < 4; kk++) {                                            \
        uint32_t af[4][4], bf[4][2];                                            \
        _Pragma("unroll")                                                       \
        for (int tm = 0; tm < 4; tm++)                                          \
            ldm_x4(af[tm][0], af[tm][1], af[tm][2], af[tm][3],                  \
                   (Ab) + (uint32_t)(ar + tm * 16) * 128u + 16u * (((kk << 1) + akh) ^ lsw)); \
        _Pragma("unroll")                                                       \
        for (int np = 0; np < 2; np++) {                                        \
            uint32_t r0, r1, r2, r3;                                            \
            ldm_x4(r0, r1, r2, r3,                                              \
                   (Bb) + (uint32_t)(br + np * 16) * 128u + 16u * (((kk << 1) + bkh) ^ lsw)); \
            bf[2*np][0] = r0; bf[2*np][1] = r1; bf[2*np+1][0] = r2; bf[2*np+1][1] = r3; \
        }                                                                       \
        _Pragma("unroll")                                                       \
        for (int tm = 0; tm < 4; tm++)                                          \
            _Pragma("unroll")                                                   \
            for (int tn = 0; tn < 4; tn++) mma_bf16(acc[tm][tn], af[tm], bf[tn]); \
    }

// ---------------- bf16 NT GEMM, 128x128 tile (proj / Wo) ----------------
__global__ __launch_bounds__(256) void gemm_bf16(
    const __nv_bfloat16* __restrict__ A, const __nv_bfloat16* __restrict__ B,
    float* __restrict__ C, int ldc, int kp)
{
    GEMM_PREAMBLE
    const int wm = wid & 1, wn = wid >> 1;
    const int m0 = blockIdx.y << 7, n0 = blockIdx.x << 7;
    const int steps = kp >> 6;
    const __nv_bfloat16* Ab_ = A + (size_t)m0 * kp;
    const __nv_bfloat16* Bb_ = B + (size_t)n0 * kp;

    float acc[4][4][4];
#pragma unroll
    for (int i = 0; i < 4; i++)
#pragma unroll
        for (int j = 0; j < 4; j++)
#pragma unroll
            for (int r = 0; r < 4; r++) acc[i][j][r] = 0.f;

    const int ar = wm * 64 + (l & 7) + (l & 8);
    const int br = wn * 32 + (l & 7) + 8 * (l >> 4);

    LOAD128(sb, Ab_, kp, 0); LOAD128(sb + 16384u, Bb_, kp, 0); cp_commit();
    LOAD128(sb + 32768u, Ab_, kp, 1); LOAD128(sb + 49152u, Bb_, kp, 1); cp_commit();

    for (int s = 0; s < steps; s++) {
        cp_wait<1>();
        __syncthreads();
        if (s + 2 < steps) {
            uint32_t b2 = sb + ((s + 2) % 3) * 32768u;
            LOAD128(b2, Ab_, kp, s + 2); LOAD128(b2 + 16384u, Bb_, kp, s + 2);
        }
        cp_commit();
        const uint32_t Ab = sb + (s % 3) * 32768u;
        const uint32_t Bb = Ab + 16384u;
        INNER_128(Ab, Bb)
    }
    const int er = m0 + wm * 64 + (l >> 2);
    const int ec = n0 + wn * 32 + 2 * (l & 3);
#pragma unroll
    for (int tm = 0; tm < 4; tm++)
#pragma unroll
        for (int tn = 0; tn < 4; tn++) {
            float* p0 = C + (size_t)(er + tm * 16) * ldc + ec + tn * 8;
            float* p1 = C + (size_t)(er + tm * 16 + 8) * ldc + ec + tn * 8;
            *(float2*)p0 = make_float2(acc[tm][tn][0], acc[tm][tn][1]);
            *(float2*)p1 = make_float2(acc[tm][tn][2], acc[tm][tn][3]);
        }
}

// ---------------- scores on tensor cores ----------------
__global__ __launch_bounds__(256) void scores_mma()
{
    GEMM_PREAMBLE
    const int wm = wid & 1, wn = wid >> 1;
    const int h = blockIdx.y, idx = blockIdx.x;
    int ti = (int)((sqrtf(8.f * idx + 1.f) - 1.f) * 0.5f);
    while ((ti + 1) * (ti + 2) / 2 <= idx) ti++;
    while (ti * (ti + 1) / 2 > idx) ti--;
    const int tj = idx - ti * (ti + 1) / 2;
    const int i0 = ti << 7, j0 = tj << 7;
    const __nv_bfloat16* Ab_ = g_qa + ((size_t)h * SDIM + i0) * KQ;
    const __nv_bfloat16* Bb_ = g_kb + ((size_t)h * SDIM + j0) * KQ;
    const int steps = KQ >> 6;

    float acc[4][4][4];
#pragma unroll
    for (int i = 0; i < 4; i++)
#pragma unroll
        for (int j = 0; j < 4; j++)
#pragma unroll
            for (int r = 0; r < 4; r++) acc[i][j][r] = 0.f;
    const int ar = wm * 64 + (l & 7) + (l & 8);
    const int br = wn * 32 + (l & 7) + 8 * (l >> 4);

    LOAD128(sb, Ab_, KQ, 0); LOAD128(sb + 16384u, Bb_, KQ, 0); cp_commit();
    LOAD128(sb + 32768u, Ab_, KQ, 1); LOAD128(sb + 49152u, Bb_, KQ, 1); cp_commit();

    for (int s = 0; s < steps; s++) {
        cp_wait<1>();
        __syncthreads();
        if (s + 2 < steps) {
            uint32_t b2 = sb + ((s + 2) % 3) * 32768u;
            LOAD128(b2, Ab_, KQ, s + 2); LOAD128(b2 + 16384u, Bb_, KQ, s + 2);
        }
        cp_commit();
        const uint32_t Ab = sb + (s % 3) * 32768u;
        const uint32_t Bb = Ab + 16384u;
        INNER_128(Ab, Bb)
    }
    const int er = i0 + wm * 64 + (l >> 2);
    const int ec = j0 + wn * 32 + 2 * (l & 3);
#pragma unroll
    for (int tm = 0; tm < 4; tm++)
#pragma unroll
        for (int tn = 0; tn < 4; tn++) {
            int r0 = er + tm * 16, r1 = r0 + 8, c = ec + tn * 8;
            float* p0 = g_sc + ((size_t)h * SDIM + r0) * SDIM + c;
            float* p1 = g_sc + ((size_t)h * SDIM + r1) * SDIM + c;
            *(float2*)p0 = make_float2(c     <= r0 ? acc[tm][tn][0] : 0.f,
                                       c + 1 <= r0 ? acc[tm][tn][1] : 0.f);
            *(float2*)p1 = make_float2(c     <= r1 ? acc[tm][tn][2] : 0.f,
                                       c + 1 <= r1 ? acc[tm][tn][3] : 0.f);
        }
}

// ---------------- AV on tensor cores; epilogue writes folded ao3 ----------
__global__ __launch_bounds__(256) void av_mma()
{
    GEMM_PREAMBLE
    const int wm = wid & 1, wn = wid >> 1;
    const int h = blockIdx.y;
    const __nv_bfloat16* Bb_ = g_vt + (size_t)(h >> 2) * DH * KA;

    for (int half = 0; half < 2; half++) {
        const int mt = half ? 31 - (int)blockIdx.x : (int)blockIdx.x;
        const int m0 = mt << 6;
        const int steps = 3 * (mt + 1);
        const __nv_bfloat16* Ab_ = g_at + ((size_t)h * SDIM + m0) * KA;

        float acc[2][4][4];
#pragma unroll
        for (int i = 0; i < 2; i++)
#pragma unroll
            for (int j = 0; j < 4; j++)
#pragma unroll
                for (int r = 0; r < 4; r++) acc[i][j][r] = 0.f;
        const int ar = wm * 32 + (l & 7) + (l & 8);
        const int br = wn * 32 + (l & 7) + 8 * (l >> 4);

        LOAD64(sb, Ab_, KA, 0); LOAD128(sb + 8192u, Bb_, KA, 0); cp_commit();
        LOAD64(sb + 24576u, Ab_, KA, 1); LOAD128(sb + 32768u, Bb_, KA, 1); cp_commit();

        for (int s = 0; s < steps; s++) {
            cp_wait<1>();
            __syncthreads();
            if (s + 2 < steps) {
                uint32_t b2 = sb + ((s + 2) % 3) * 24576u;
                LOAD64(b2, Ab_, KA, s + 2); LOAD128(b2 + 8192u, Bb_, KA, s + 2);
            }
            cp_commit();
            const uint32_t Ab = sb + (s % 3) * 24576u;
            const uint32_t Bb = Ab + 8192u;
#pragma unroll
            for (int kk = 0; kk < 4; kk++) {
                uint32_t af[2][4], bf[4][2];
#pragma unroll
                for (int tm = 0; tm < 2; tm++)
                    ldm_x4(af[tm][0], af[tm][1], af[tm][2], af[tm][3],
                           Ab + (uint32_t)(ar + tm * 16) * 128u + 16u * (((kk << 1) + akh) ^ lsw));
#pragma unroll
                for (int np = 0; np < 2; np++) {
                    uint32_t r0, r1, r2, r3;
                    ldm_x4(r0, r1, r2, r3,
                           Bb + (uint32_t)(br + np * 16) * 128u + 16u * (((kk << 1) + bkh) ^ lsw));
                    bf[2*np][0] = r0; bf[2*np][1] = r1; bf[2*np+1][0] = r2; bf[2*np+1][1] = r3;
                }
#pragma unroll
                for (int tm = 0; tm < 2; tm++)
#pragma unroll
                    for (int tn = 0; tn < 4; tn++) mma_bf16(acc[tm][tn], af[tm], bf[tn]);
            }
        }
        // epilogue: fold fp32 pairs directly into ao3 (A-side pattern h,h,l)
        const int er = m0 + wm * 32 + (l >> 2);
        const int ecl = wn * 32 + 2 * (l & 3);
#pragma unroll
        for (int tm = 0; tm < 2; tm++)
#pragma unroll
            for (int tn = 0; tn < 4; tn++) {
                int c = h * DH + ecl + tn * 8;          // even
                int r0 = er + tm * 16, r1 = r0 + 8;
#pragma unroll
                for (int rr = 0; rr < 2; rr++) {
                    int row = rr ? r1 : r0;
                    float v0 = acc[tm][tn][rr ? 2 : 0];
                    float v1 = acc[tm][tn][rr ? 3 : 1];
                    uint32_t H0, L0, H1, L1;
                    fold2(v0, H0, L0); fold2(v1, H1, L1);
                    uint32_t* o = (uint32_t*)g_ao3 + (size_t)row * (KP / 2) + 3 * (c / 2);
                    o[0] = H0 | (H0 << 16);
                    o[1] = L0 | (H1 << 16);
                    o[2] = H1 | (L1 << 16);
                }
            }
        __syncthreads();
    }
}

// ---------------- fused RMSNorm + RoPE + fold into qa ----------------
__global__ __launch_bounds__(128) void norm_fill_qa(
    const float* __restrict__ w, const float* __restrict__ gscale)
{
    const int s = blockIdx.x, h = blockIdx.y, d = threadIdx.x;
    float v = g_pr[(size_t)s * NOUT + CQ + h * DH + d];
    float ss = v * v;
#pragma unroll
    for (int o = 16; o; o >>= 1) ss += __shfl_xor_sync(0xffffffffu, ss, o);
    __shared__ float r4[4];
    __shared__ float sh[DH];
    if ((d & 31) == 0) r4[d >> 5] = ss;
    __syncthreads();
    float nv = v * rsqrtf((r4[0]+r4[1]+r4[2]+r4[3]) * (1.f / DH) + 1e-6f) * w[d];
    sh[d] = nv;
    __syncthreads();
    const int dm = d & 63;
    float f = 1.f / powf(10000.f, (float)(2 * dm) * (1.f / DH));
    float cs, sn; sincosf((float)s * f, &sn, &cs);
    float rot = (d < 64) ? -sh[d + 64] : sh[d - 64];
    float qs = (nv * cs + rot * sn) * 0.08838834764831845f;

    __nv_bfloat16* row = g_qa + ((size_t)h * SDIM + s) * KQ;
    uint32_t H, L; fold2(qs, H, L);
    row[3*d]   = __ushort_as_bfloat16((unsigned short)H);
    row[3*d+1] = __ushort_as_bfloat16((unsigned short)H);
    row[3*d+2] = __ushort_as_bfloat16((unsigned short)L);
    if (d < 32) {
        float bv = 0.f;
        if (h < NHG) bv = gscale[h] * (h < NSYM ? 0.5f : 1.f)
                         * g_pr[(size_t)s * NOUT + CRQ + h * RDIM + d];
        row[384 + d] = __float2bfloat16(bv);
    } else if (d < 64) {
        int r = d - 32;
        float bv = 0.f;
        if (h < NSYM) bv = gscale[h] * 0.5f * g_pr[(size_t)s * NOUT + CRK + h * RDIM + r];
        row[416 + r] = __float2bfloat16(bv);
    }
}

// ---------------- fused RMSNorm + RoPE + fold into kb (4 heads/kvh) --------
__global__ __launch_bounds__(128) void norm_fill_kb(const float* __restrict__ w)
{
    const int s = blockIdx.x, kvh = blockIdx.y, d = threadIdx.x;
    float v = g_pr[(size_t)s * NOUT + CK + kvh * DH + d];
    float ss = v * v;
#pragma unroll
    for (int o = 16; o; o >>= 1) ss += __shfl_xor_sync(0xffffffffu, ss, o);
    __shared__ float r4[4];
    __shared__ float sh[DH];
    if ((d & 31) == 0) r4[d >> 5] = ss;
    __syncthreads();
    float nv = v * rsqrtf((r4[0]+r4[1]+r4[2]+r4[3]) * (1.f / DH) + 1e-6f) * w[d];
    sh[d] = nv;
    __syncthreads();
    const int dm = d & 63;
    float f = 1.f / powf(10000.f, (float)(2 * dm) * (1.f / DH));
    float cs, sn; sincosf((float)s * f, &sn, &cs);
    float rot = (d < 64) ? -sh[d + 64] : sh[d - 64];
    float kf = nv * cs + rot * sn;
    uint32_t H, L; fold2(kf, H, L);

#pragma unroll
    for (int e = 0; e < 4; e++) {
        int h = kvh * 4 + e;
        __nv_bfloat16* row = g_kb + ((size_t)h * SDIM + s) * KQ;
        row[3*d]   = __ushort_as_bfloat16((unsigned short)H);
        row[3*d+1] = __ushort_as_bfloat16((unsigned short)L);
        row[3*d+2] = __ushort_as_bfloat16((unsigned short)H);
        if (d < 32) {
            float bv = (h < NHG) ? g_pr[(size_t)s * NOUT + CRK + h * RDIM + d] : 0.f;
            row[384 + d] = __float2bfloat16(bv);
        } else if (d < 64) {
            int r = d - 32;
            float bv = (h < NSYM) ? g_pr[(size_t)s * NOUT + CRQ + h * RDIM + r] : 0.f;
            row[416 + r] = __float2bfloat16(bv);
        }
    }
}

// ---------------- fill vt (smem transpose + B-side fold) ----------------
__global__ __launch_bounds__(128) void fill_vt()
{
    __shared__ float sm[32][33];
    const int jb = blockIdx.x, kvh = blockIdx.y, d = threadIdx.x;
    for (int c = 0; c < 4; c++) {
        int j0 = jb * 128 + c * 32;
        for (int r = 0; r < 32; r++)
            sm[r][d & 31] = (d < 128) ? 0.f : 0.f;  // placeholder avoid unused warn
        __syncthreads();
        for (int r = 0; r < 32; r++)
            if (d < 128) sm[r][0] = sm[r][0];       // no-op
        __syncthreads();
        // actual: load 32 rows x 128 cols via two half-tiles of 32x32? simpler direct:
        // (each thread d loads column d over 32 rows -> strided; acceptable given tiny size)
        uint32_t* row = (uint32_t*)g_vt + ((size_t)(kvh * DH + d) * KA + 3 * (size_t)j0) / 2;
        for (int r2 = 0; r2 < 16; r2++) {
            float v0 = g_pr[(size_t)(j0 + 2*r2)     * NOUT + CV + kvh * DH + d];
            float v1 = g_pr[(size_t)(j0 + 2*r2 + 1) * NOUT + CV + kvh * DH + d];
            uint32_t H0, L0, H1, L1;
            fold2(v0, H0, L0); fold2(v1, H1, L1);
            row[3*r2]   = H0 | (L0 << 16);
            row[3*r2+1] = H0 | (H1 << 16);
            row[3*r2+2] = L1 | (H1 << 16);
        }
        __syncthreads();
    }
}

// ---------------- softmax: read scores fp32, write folded attn -------------
__global__ __launch_bounds__(256) void softmax_kernel()
{
    const int i = blockIdx.x, h = blockIdx.y;
    const int len = i + 1;
    const int lenp = (len + 127) & ~127;
    const float* row = g_sc + ((size_t)h * SDIM + i) * SDIM;
    __shared__ float buf[SDIM];
    __shared__ float red[8];
    const int tid = threadIdx.x;

    float m = -3.4e38f;
    for (int j = tid; j < len; j += 256) { float v = row[j]; buf[j] = v; m = fmaxf(m, v); }
#pragma unroll
    for (int o = 16; o; o >>= 1) m = fmaxf(m, __shfl_xor_sync(0xffffffffu, m, o));
    if ((tid & 31) == 0) red[tid >> 5] = m;
    __syncthreads();
    m = red[0];
#pragma unroll
    for (int q = 1; q < 8; q++) m = fmaxf(m, red[q]);
    __syncthreads();

    float sum = 0.f;
    for (int j = tid; j < len; j += 256) { float e = __expf(buf[j] - m); buf[j] = e; sum += e; }
#pragma unroll
    for (int o = 16; o; o >>= 1) sum += __shfl_xor_sync(0xffffffffu, sum, o);
    if ((tid & 31) == 0) red[tid >> 5] = sum;
    __syncthreads();
    sum = red[0] + red[1] + red[2] + red[3] + red[4] + red[5] + red[6] + red[7];
    const float inv = 1.f / sum;
    __syncthreads();

    uint32_t* orow = (uint32_t*)g_at + ((size_t)h * SDIM + i) * (KA / 2);
    for (int j2 = tid; j2 < (lenp >> 1); j2 += 256) {
        int j0 = 2 * j2;
        float a0 = (j0 < len)     ? buf[j0] * inv     : 0.f;
        float a1 = (j0 + 1 < len) ? buf[j0 + 1] * inv : 0.f;
        uint32_t H0, L0, H1, L1;
        fold2(a0, H0, L0); fold2(a1, H1, L1);
        orow[3*j2]   = H0 | (H0 << 16);
        orow[3*j2+1] = L0 | (H1 << 16);
        orow[3*j2+2] = H1 | (L1 << 16);
    }
}

// ---------------- Host ----------------
extern "C" void kernel_launch(void* const* d_in, const int* in_sizes, int n_in,
                              void* d_out, int out_size)
{
    const float* x   = (const float*)d_in[0];
    const float* Wq  = (const float*)d_in[1];
    const float* Wk  = (const float*)d_in[2];
    const float* Wv  = (const float*)d_in[3];
    const float* Wo  = (const float*)d_in[4];
    const float* qnw = (const float*)d_in[5];
    const float* knw = (const float*)d_in[6];
    const float* Wrq = (const float*)d_in[7];
    const float* Wrk = (const float*)d_in[8];
    const float* gsc = (const float*)d_in[9];
    float* out = (float*)d_out;

    float* pr;
    __nv_bfloat16 *x3, *ao3, *w3, *wo3;
    cudaGetSymbolAddress((void**)&pr,  g_pr);
    cudaGetSymbolAddress((void**)&x3,  g_x3);
    cudaGetSymbolAddress((void**)&ao3, g_ao3);
    cudaGetSymbolAddress((void**)&w3,  g_w3);
    cudaGetSymbolAddress((void**)&wo3, g_wo3);

    cudaFuncSetAttribute(gemm_bf16,  cudaFuncAttributeMaxDynamicSharedMemorySize, 98304);
    cudaFuncSetAttribute(scores_mma, cudaFuncAttributeMaxDynamicSharedMemorySize, 98304);
    cudaFuncSetAttribute(av_mma,     cudaFuncAttributeMaxDynamicSharedMemorySize, 73728);

    // 5 split launches, so launch #5 (0-based) = projection GEMM for ncu -s 5
    split_pair<<<8192, 256>>>(x,  x3,                    SDIM*EDIM/2, 0);
    split_pair<<<8192, 256>>>(Wq, w3 + (size_t)CQ * KP,  EDIM*EDIM/2, 1);
    split2<<<4096, 256>>>(Wk,  w3 + (size_t)CK  * KP, 512*EDIM/2,
                          Wv,  w3 + (size_t)CV  * KP, 512*EDIM/2);
    split2<<<3072, 256>>>(Wrq, w3 + (size_t)CRQ * KP, 384*EDIM/2,
                          Wrk, w3 + (size_t)CRK * KP, 384*EDIM/2);
    split_pair<<<8192, 256>>>(Wo, wo3, EDIM*EDIM/2, 1);

    gemm_bf16<<<dim3(NOUT/128, 16), 256, 98304>>>(x3, w3, pr, NOUT, KP);

    norm_fill_qa<<<dim3(SDIM, NH),  128>>>(qnw, gsc);
    norm_fill_kb<<<dim3(SDIM, NKV), 128>>>(knw);
    fill_vt<<<dim3(SDIM/128, NKV), 128>>>();

    scores_mma<<<dim3(136, NH), 256, 98304>>>();
    softmax_kernel<<<dim3(SDIM, NH), 256>>>();
    av_mma<<<dim3(16, NH), 256, 73728>>>();

    gemm_bf16<<<dim3(16, 16), 256, 98304>>>(ao3, wo3, out, EDIM, KP);
}